// round 2
// baseline (speedup 1.0000x reference)
#include <cuda_runtime.h>
#include <math_constants.h>

typedef unsigned long long u64;

#define B_ 8
#define T_ 2048
#define C_ 1024
#define H_ 64
#define M_ (B_*T_)

// Projected q/k/v stored as interleaved complex (re,im) packed in 64 bits.
__device__ u64 g_q[M_*H_];
__device__ u64 g_k[M_*H_];
__device__ u64 g_v[M_*H_];

// ---- f32x2 packed-math helpers (FFMA2 is PTX-only; ptxas never auto-fuses) ----
__device__ __forceinline__ u64 pack2(float lo, float hi) {
    u64 r; asm("mov.b64 %0, {%1, %2};" : "=l"(r) : "f"(lo), "f"(hi)); return r;
}
__device__ __forceinline__ void unpack2(u64 v, float& lo, float& hi) {
    asm("mov.b64 {%0, %1}, %2;" : "=f"(lo), "=f"(hi) : "l"(v));
}
__device__ __forceinline__ u64 fma2(u64 a, u64 b, u64 c) {
    u64 d; asm("fma.rn.f32x2 %0, %1, %2, %3;" : "=l"(d) : "l"(a), "l"(b), "l"(c)); return d;
}
__device__ __forceinline__ u64 mul2(u64 a, u64 b) {
    u64 d; asm("mul.rn.f32x2 %0, %1, %2;" : "=l"(d) : "l"(a), "l"(b)); return d;
}

// ---------------------------------------------------------------------------
// Projection: (xr + i xi) @ (Wr + i Wi) for k,q,v fused. 64 rows/block,
// 16 rows/thread, packed f32x2 complex accumulation.
//   acc(re,im) += (ar,ai)*(wr,wr);  acc += (ai,ar)*(-wi,wi)
// ---------------------------------------------------------------------------
__global__ __launch_bounds__(256) void proj_kernel(
    const float* __restrict__ xr,  const float* __restrict__ xi,
    const float* __restrict__ Wkr, const float* __restrict__ Wki,
    const float* __restrict__ Wqr, const float* __restrict__ Wqi,
    const float* __restrict__ Wvr, const float* __restrict__ Wvi)
{
    __shared__ float2 sx[64][33];

    const int tid = threadIdx.x;
    const int h   = tid & 63;
    const int rg  = tid >> 6;           // 0..3 -> 16 rows each
    const int m0  = blockIdx.x * 64;

    u64 ak[16], aq[16], av[16];
    const u64 z = pack2(0.f, 0.f);
    #pragma unroll
    for (int r = 0; r < 16; ++r) { ak[r]=z; aq[r]=z; av[r]=z; }

    for (int c0 = 0; c0 < C_; c0 += 32) {
        __syncthreads();
        #pragma unroll
        for (int i = tid; i < 64*32; i += 256) {
            int r = i >> 5, c = i & 31;
            size_t g = (size_t)(m0 + r)*C_ + c0 + c;
            sx[r][c] = make_float2(xr[g], xi[g]);
        }
        __syncthreads();

        #pragma unroll 2
        for (int c = 0; c < 32; ++c) {
            const int wo = (c0 + c)*H_ + h;
            const float wkr = Wkr[wo], wki = Wki[wo];
            const float wqr = Wqr[wo], wqi = Wqi[wo];
            const float wvr = Wvr[wo], wvi = Wvi[wo];
            const u64 w1k = pack2(wkr,  wkr), w2k = pack2(-wki, wki);
            const u64 w1q = pack2(wqr,  wqr), w2q = pack2(-wqi, wqi);
            const u64 w1v = pack2(wvr,  wvr), w2v = pack2(-wvi, wvi);
            #pragma unroll
            for (int r = 0; r < 16; ++r) {
                const float2 xv = sx[rg*16 + r][c];
                const u64 v1 = pack2(xv.x, xv.y);   // (ar, ai)
                const u64 v2 = pack2(xv.y, xv.x);   // (ai, ar)
                ak[r] = fma2(v1, w1k, ak[r]); ak[r] = fma2(v2, w2k, ak[r]);
                aq[r] = fma2(v1, w1q, aq[r]); aq[r] = fma2(v2, w2q, aq[r]);
                av[r] = fma2(v1, w1v, av[r]); av[r] = fma2(v2, w2v, av[r]);
            }
        }
    }

    #pragma unroll
    for (int r = 0; r < 16; ++r) {
        const size_t o = (size_t)(m0 + rg*16 + r)*H_ + h;
        g_k[o] = ak[r]; g_q[o] = aq[r]; g_v[o] = av[r];
    }
}

// ---------------------------------------------------------------------------
// Flash-style complex attention, f32x2 packed.
// Scores:  (sr,si) += (qr,qi)*(kr,kr) + (qi,-qr)*(ki,ki)
// PV:      (or,oi) += (p,p)*(vr,vi)
// ---------------------------------------------------------------------------
#define QST 68
#define VST 66
#define PST 68

struct AttnSmem {
    float Qr[64][QST], Qi[64][QST];   // [h][q]
    float Kr[64][QST], Ki[64][QST];   // [h][k]
    u64   Vc[64][VST];                // [k][h] packed (vr,vi)
    float P [64][PST];                // [k][q]
    float M[64], L[64];
};

__global__ __launch_bounds__(256) void attn_kernel(float* __restrict__ out)
{
    extern __shared__ char smem_raw[];
    AttnSmem& s = *reinterpret_cast<AttnSmem*>(smem_raw);

    const int b   = blockIdx.y;
    const int qt  = (int)gridDim.x - 1 - (int)blockIdx.x;  // heavy tiles first
    const int tid = threadIdx.x;
    const int tx  = tid & 15;
    const int ty  = tid >> 4;
    const int qbase = b*T_ + qt*64;

    for (int i = tid; i < 64*64; i += 256) {
        int row = i >> 6, hh = i & 63;
        float qr, qi;
        unpack2(g_q[(size_t)(qbase+row)*H_ + hh], qr, qi);
        s.Qr[hh][row] = qr; s.Qi[hh][row] = qi;
    }
    if (tid < 64) { s.M[tid] = -CUDART_INF_F; s.L[tid] = 0.f; }

    u64 o2[4][4];
    const u64 z = pack2(0.f, 0.f);
    #pragma unroll
    for (int a=0;a<4;a++)
        #pragma unroll
        for (int c=0;c<4;c++) o2[a][c] = z;

    for (int kt = 0; kt <= qt; ++kt) {
        __syncthreads();   // protect K/V/P from previous iteration readers
        const int kbase = b*T_ + kt*64;
        for (int i = tid; i < 64*64; i += 256) {
            int row = i >> 6, hh = i & 63;
            float kr, ki;
            unpack2(g_k[(size_t)(kbase+row)*H_ + hh], kr, ki);
            s.Kr[hh][row] = kr; s.Ki[hh][row] = ki;
            s.Vc[row][hh]  = g_v[(size_t)(kbase+row)*H_ + hh];
        }
        __syncthreads();

        // --- complex scores over H, packed (sr,si) ---
        u64 s2[4][4];
        #pragma unroll
        for (int a=0;a<4;a++)
            #pragma unroll
            for (int c=0;c<4;c++) s2[a][c] = z;

        #pragma unroll 4
        for (int hh = 0; hh < H_; ++hh) {
            const float4 q4r = *(const float4*)&s.Qr[hh][ty*4];
            const float4 q4i = *(const float4*)&s.Qi[hh][ty*4];
            const float4 k4r = *(const float4*)&s.Kr[hh][tx*4];
            const float4 k4i = *(const float4*)&s.Ki[hh][tx*4];
            u64 q1[4], q2[4], k1[4], k2[4];
            q1[0]=pack2(q4r.x,q4i.x); q2[0]=pack2(q4i.x,-q4r.x);
            q1[1]=pack2(q4r.y,q4i.y); q2[1]=pack2(q4i.y,-q4r.y);
            q1[2]=pack2(q4r.z,q4i.z); q2[2]=pack2(q4i.z,-q4r.z);
            q1[3]=pack2(q4r.w,q4i.w); q2[3]=pack2(q4i.w,-q4r.w);
            k1[0]=pack2(k4r.x,k4r.x); k2[0]=pack2(k4i.x,k4i.x);
            k1[1]=pack2(k4r.y,k4r.y); k2[1]=pack2(k4i.y,k4i.y);
            k1[2]=pack2(k4r.z,k4r.z); k2[2]=pack2(k4i.z,k4i.z);
            k1[3]=pack2(k4r.w,k4r.w); k2[3]=pack2(k4i.w,k4i.w);
            #pragma unroll
            for (int a=0;a<4;a++)
                #pragma unroll
                for (int c=0;c<4;c++) {
                    s2[a][c] = fma2(q1[a], k1[c], s2[a][c]);
                    s2[a][c] = fma2(q2[a], k2[c], s2[a][c]);
                }
        }

        // --- magnitude + causal mask + row max ---
        float p[4][4], rowmax[4];
        #pragma unroll
        for (int a=0;a<4;a++) rowmax[a] = -CUDART_INF_F;
        #pragma unroll
        for (int a=0;a<4;a++) {
            const int qg = qt*64 + ty*4 + a;
            #pragma unroll
            for (int c=0;c<4;c++) {
                const int kg = kt*64 + tx*4 + c;
                float sr, si;
                unpack2(s2[a][c], sr, si);
                const float m2 = fmaf(sr, sr, fmaf(si, si, 1e-4f));
                float v = m2 * rsqrtf(m2) * 0.125f;   // sqrt via MUFU.RSQ
                v = (kg <= qg) ? v : -CUDART_INF_F;
                p[a][c] = v;
                rowmax[a] = fmaxf(rowmax[a], v);
            }
        }
        #pragma unroll
        for (int off = 8; off; off >>= 1)
            #pragma unroll
            for (int a=0;a<4;a++)
                rowmax[a] = fmaxf(rowmax[a],
                                  __shfl_xor_sync(0xffffffffu, rowmax[a], off));

        // --- online softmax stats ---
        float m_new[4], scale[4], rowsum[4];
        #pragma unroll
        for (int a=0;a<4;a++) {
            const float m_old = s.M[ty*4+a];
            m_new[a]  = fmaxf(m_old, rowmax[a]);
            scale[a]  = __expf(m_old - m_new[a]);   // exp(-inf)=0 first tile
            rowsum[a] = 0.f;
        }
        #pragma unroll
        for (int a=0;a<4;a++)
            #pragma unroll
            for (int c=0;c<4;c++) {
                const float e = __expf(p[a][c] - m_new[a]);  // masked -> 0
                p[a][c] = e;
                rowsum[a] += e;
            }
        #pragma unroll
        for (int off = 8; off; off >>= 1)
            #pragma unroll
            for (int a=0;a<4;a++)
                rowsum[a] += __shfl_xor_sync(0xffffffffu, rowsum[a], off);

        __syncwarp();
        if (tx == 0) {
            #pragma unroll
            for (int a=0;a<4;a++) {
                s.M[ty*4+a] = m_new[a];
                s.L[ty*4+a] = s.L[ty*4+a]*scale[a] + rowsum[a];
            }
        }

        // rescale packed accumulators
        #pragma unroll
        for (int a=0;a<4;a++) {
            const u64 sc = pack2(scale[a], scale[a]);
            #pragma unroll
            for (int c=0;c<4;c++) o2[a][c] = mul2(o2[a][c], sc);
        }

        // stage P transposed [k][q]
        #pragma unroll
        for (int a=0;a<4;a++)
            #pragma unroll
            for (int c=0;c<4;c++)
                s.P[tx*4+c][ty*4+a] = p[a][c];
        __syncthreads();

        // --- O += P @ V, packed (or,oi) ---
        #pragma unroll 4
        for (int kk = 0; kk < 64; ++kk) {
            const float4 p4 = *(const float4*)&s.P[kk][ty*4];
            const ulonglong2 va = *(const ulonglong2*)&s.Vc[kk][tx*4];
            const ulonglong2 vb = *(const ulonglong2*)&s.Vc[kk][tx*4+2];
            const u64 vv[4] = {va.x, va.y, vb.x, vb.y};
            const u64 pp[4] = {pack2(p4.x,p4.x), pack2(p4.y,p4.y),
                               pack2(p4.z,p4.z), pack2(p4.w,p4.w)};
            #pragma unroll
            for (int a=0;a<4;a++)
                #pragma unroll
                for (int c=0;c<4;c++)
                    o2[a][c] = fma2(pp[a], vv[c], o2[a][c]);
        }
    }

    __syncthreads();
    float inv[4];
    #pragma unroll
    for (int a=0;a<4;a++) inv[a] = 1.f / s.L[ty*4+a];

    #pragma unroll
    for (int a=0;a<4;a++) {
        const size_t row = (size_t)(qbase + ty*4 + a);
        float4 vr, vi;
        float orv, oiv;
        unpack2(o2[a][0], orv, oiv); vr.x = orv*inv[a]; vi.x = oiv*inv[a];
        unpack2(o2[a][1], orv, oiv); vr.y = orv*inv[a]; vi.y = oiv*inv[a];
        unpack2(o2[a][2], orv, oiv); vr.z = orv*inv[a]; vi.z = oiv*inv[a];
        unpack2(o2[a][3], orv, oiv); vr.w = orv*inv[a]; vi.w = oiv*inv[a];
        *(float4*)&out[row*H_ + tx*4]                 = vr;   // out_real
        *(float4*)&out[(size_t)M_*H_ + row*H_ + tx*4] = vi;   // out_imag
    }
}

// ---------------------------------------------------------------------------
extern "C" void kernel_launch(void* const* d_in, const int* in_sizes, int n_in,
                              void* d_out, int out_size)
{
    const float* xr  = (const float*)d_in[0];
    const float* xi  = (const float*)d_in[1];
    const float* Wkr = (const float*)d_in[2];
    const float* Wki = (const float*)d_in[3];
    const float* Wqr = (const float*)d_in[4];
    const float* Wqi = (const float*)d_in[5];
    const float* Wvr = (const float*)d_in[6];
    const float* Wvi = (const float*)d_in[7];

    cudaFuncSetAttribute(attn_kernel,
                         cudaFuncAttributeMaxDynamicSharedMemorySize,
                         (int)sizeof(AttnSmem));

    proj_kernel<<<M_/64, 256>>>(xr, xi, Wkr, Wki, Wqr, Wqi, Wvr, Wvi);

    dim3 ag(T_/64, B_);
    attn_kernel<<<ag, 256, sizeof(AttnSmem)>>>((float*)d_out);
}

// round 3
// speedup vs baseline: 1.0049x; 1.0049x over previous
#include <cuda_runtime.h>
#include <math_constants.h>

typedef unsigned long long u64;

#define B_ 8
#define T_ 2048
#define C_ 1024
#define H_ 64
#define M_ (B_*T_)

// Projected q/k/v stored as interleaved complex (re,im) packed in 64 bits.
__device__ u64 g_q[M_*H_];
__device__ u64 g_k[M_*H_];
__device__ u64 g_v[M_*H_];

// ---- f32x2 packed-math helpers (FFMA2 is PTX-only; ptxas never auto-fuses) ----
__device__ __forceinline__ u64 pack2(float lo, float hi) {
    u64 r; asm("mov.b64 %0, {%1, %2};" : "=l"(r) : "f"(lo), "f"(hi)); return r;
}
__device__ __forceinline__ void unpack2(u64 v, float& lo, float& hi) {
    asm("mov.b64 {%0, %1}, %2;" : "=f"(lo), "=f"(hi) : "l"(v));
}
__device__ __forceinline__ u64 fma2(u64 a, u64 b, u64 c) {
    u64 d; asm("fma.rn.f32x2 %0, %1, %2, %3;" : "=l"(d) : "l"(a), "l"(b), "l"(c)); return d;
}
__device__ __forceinline__ u64 mul2(u64 a, u64 b) {
    u64 d; asm("mul.rn.f32x2 %0, %1, %2;" : "=l"(d) : "l"(a), "l"(b)); return d;
}

// ---------------------------------------------------------------------------
// Projection: (xr + i xi) @ (Wr + i Wi) for k,q,v fused. 64 rows/block,
// 16 rows/thread, packed f32x2 complex accumulation.
//   acc(re,im) += (ar,ai)*(wr,wr);  acc += (ai,ar)*(-wi,wi)
// ---------------------------------------------------------------------------
__global__ __launch_bounds__(256) void proj_kernel(
    const float* __restrict__ xr,  const float* __restrict__ xi,
    const float* __restrict__ Wkr, const float* __restrict__ Wki,
    const float* __restrict__ Wqr, const float* __restrict__ Wqi,
    const float* __restrict__ Wvr, const float* __restrict__ Wvi)
{
    __shared__ float2 sx[64][33];

    const int tid = threadIdx.x;
    const int h   = tid & 63;
    const int rg  = tid >> 6;           // 0..3 -> 16 rows each
    const int m0  = blockIdx.x * 64;

    u64 ak[16], aq[16], av[16];
    const u64 z = pack2(0.f, 0.f);
    #pragma unroll
    for (int r = 0; r < 16; ++r) { ak[r]=z; aq[r]=z; av[r]=z; }

    for (int c0 = 0; c0 < C_; c0 += 32) {
        __syncthreads();
        #pragma unroll
        for (int i = tid; i < 64*32; i += 256) {
            int r = i >> 5, c = i & 31;
            size_t g = (size_t)(m0 + r)*C_ + c0 + c;
            sx[r][c] = make_float2(xr[g], xi[g]);
        }
        __syncthreads();

        #pragma unroll 2
        for (int c = 0; c < 32; ++c) {
            const int wo = (c0 + c)*H_ + h;
            const float wkr = Wkr[wo], wki = Wki[wo];
            const float wqr = Wqr[wo], wqi = Wqi[wo];
            const float wvr = Wvr[wo], wvi = Wvi[wo];
            const u64 w1k = pack2(wkr,  wkr), w2k = pack2(-wki, wki);
            const u64 w1q = pack2(wqr,  wqr), w2q = pack2(-wqi, wqi);
            const u64 w1v = pack2(wvr,  wvr), w2v = pack2(-wvi, wvi);
            #pragma unroll
            for (int r = 0; r < 16; ++r) {
                const float2 xv = sx[rg*16 + r][c];
                const u64 v1 = pack2(xv.x, xv.y);   // (ar, ai)
                const u64 v2 = pack2(xv.y, xv.x);   // (ai, ar)
                ak[r] = fma2(v1, w1k, ak[r]); ak[r] = fma2(v2, w2k, ak[r]);
                aq[r] = fma2(v1, w1q, aq[r]); aq[r] = fma2(v2, w2q, aq[r]);
                av[r] = fma2(v1, w1v, av[r]); av[r] = fma2(v2, w2v, av[r]);
            }
        }
    }

    #pragma unroll
    for (int r = 0; r < 16; ++r) {
        const size_t o = (size_t)(m0 + rg*16 + r)*H_ + h;
        g_k[o] = ak[r]; g_q[o] = aq[r]; g_v[o] = av[r];
    }
}

// ---------------------------------------------------------------------------
// Flash-style complex attention, f32x2 packed.
// Scores:  (sr,si) += (qr,qi)*(kr,kr) + (qi,-qr)*(ki,ki)
// PV:      (or,oi) += (p,p)*(vr,vi)
// ---------------------------------------------------------------------------
#define QST 68
#define VST 66
#define PST 68

struct AttnSmem {
    float Qr[64][QST], Qi[64][QST];   // [h][q]
    float Kr[64][QST], Ki[64][QST];   // [h][k]
    u64   Vc[64][VST];                // [k][h] packed (vr,vi)
    float P [64][PST];                // [k][q]
    float M[64], L[64];
};

__global__ __launch_bounds__(256) void attn_kernel(float* __restrict__ out)
{
    extern __shared__ char smem_raw[];
    AttnSmem& s = *reinterpret_cast<AttnSmem*>(smem_raw);

    const int b   = blockIdx.y;
    const int qt  = (int)gridDim.x - 1 - (int)blockIdx.x;  // heavy tiles first
    const int tid = threadIdx.x;
    const int tx  = tid & 15;
    const int ty  = tid >> 4;
    const int qbase = b*T_ + qt*64;

    for (int i = tid; i < 64*64; i += 256) {
        int row = i >> 6, hh = i & 63;
        float qr, qi;
        unpack2(g_q[(size_t)(qbase+row)*H_ + hh], qr, qi);
        s.Qr[hh][row] = qr; s.Qi[hh][row] = qi;
    }
    if (tid < 64) { s.M[tid] = -CUDART_INF_F; s.L[tid] = 0.f; }

    u64 o2[4][4];
    const u64 z = pack2(0.f, 0.f);
    #pragma unroll
    for (int a=0;a<4;a++)
        #pragma unroll
        for (int c=0;c<4;c++) o2[a][c] = z;

    for (int kt = 0; kt <= qt; ++kt) {
        __syncthreads();   // protect K/V/P from previous iteration readers
        const int kbase = b*T_ + kt*64;
        for (int i = tid; i < 64*64; i += 256) {
            int row = i >> 6, hh = i & 63;
            float kr, ki;
            unpack2(g_k[(size_t)(kbase+row)*H_ + hh], kr, ki);
            s.Kr[hh][row] = kr; s.Ki[hh][row] = ki;
            s.Vc[row][hh]  = g_v[(size_t)(kbase+row)*H_ + hh];
        }
        __syncthreads();

        // --- complex scores over H, packed (sr,si) ---
        u64 s2[4][4];
        #pragma unroll
        for (int a=0;a<4;a++)
            #pragma unroll
            for (int c=0;c<4;c++) s2[a][c] = z;

        #pragma unroll 4
        for (int hh = 0; hh < H_; ++hh) {
            const float4 q4r = *(const float4*)&s.Qr[hh][ty*4];
            const float4 q4i = *(const float4*)&s.Qi[hh][ty*4];
            const float4 k4r = *(const float4*)&s.Kr[hh][tx*4];
            const float4 k4i = *(const float4*)&s.Ki[hh][tx*4];
            u64 q1[4], q2[4], k1[4], k2[4];
            q1[0]=pack2(q4r.x,q4i.x); q2[0]=pack2(q4i.x,-q4r.x);
            q1[1]=pack2(q4r.y,q4i.y); q2[1]=pack2(q4i.y,-q4r.y);
            q1[2]=pack2(q4r.z,q4i.z); q2[2]=pack2(q4i.z,-q4r.z);
            q1[3]=pack2(q4r.w,q4i.w); q2[3]=pack2(q4i.w,-q4r.w);
            k1[0]=pack2(k4r.x,k4r.x); k2[0]=pack2(k4i.x,k4i.x);
            k1[1]=pack2(k4r.y,k4r.y); k2[1]=pack2(k4i.y,k4i.y);
            k1[2]=pack2(k4r.z,k4r.z); k2[2]=pack2(k4i.z,k4i.z);
            k1[3]=pack2(k4r.w,k4r.w); k2[3]=pack2(k4i.w,k4i.w);
            #pragma unroll
            for (int a=0;a<4;a++)
                #pragma unroll
                for (int c=0;c<4;c++) {
                    s2[a][c] = fma2(q1[a], k1[c], s2[a][c]);
                    s2[a][c] = fma2(q2[a], k2[c], s2[a][c]);
                }
        }

        // --- magnitude + causal mask + row max ---
        float p[4][4], rowmax[4];
        #pragma unroll
        for (int a=0;a<4;a++) rowmax[a] = -CUDART_INF_F;
        #pragma unroll
        for (int a=0;a<4;a++) {
            const int qg = qt*64 + ty*4 + a;
            #pragma unroll
            for (int c=0;c<4;c++) {
                const int kg = kt*64 + tx*4 + c;
                float sr, si;
                unpack2(s2[a][c], sr, si);
                const float m2 = fmaf(sr, sr, fmaf(si, si, 1e-4f));
                float v = m2 * rsqrtf(m2) * 0.125f;   // sqrt via MUFU.RSQ
                v = (kg <= qg) ? v : -CUDART_INF_F;
                p[a][c] = v;
                rowmax[a] = fmaxf(rowmax[a], v);
            }
        }
        #pragma unroll
        for (int off = 8; off; off >>= 1)
            #pragma unroll
            for (int a=0;a<4;a++)
                rowmax[a] = fmaxf(rowmax[a],
                                  __shfl_xor_sync(0xffffffffu, rowmax[a], off));

        // --- online softmax stats ---
        float m_new[4], scale[4], rowsum[4];
        #pragma unroll
        for (int a=0;a<4;a++) {
            const float m_old = s.M[ty*4+a];
            m_new[a]  = fmaxf(m_old, rowmax[a]);
            scale[a]  = __expf(m_old - m_new[a]);   // exp(-inf)=0 first tile
            rowsum[a] = 0.f;
        }
        #pragma unroll
        for (int a=0;a<4;a++)
            #pragma unroll
            for (int c=0;c<4;c++) {
                const float e = __expf(p[a][c] - m_new[a]);  // masked -> 0
                p[a][c] = e;
                rowsum[a] += e;
            }
        #pragma unroll
        for (int off = 8; off; off >>= 1)
            #pragma unroll
            for (int a=0;a<4;a++)
                rowsum[a] += __shfl_xor_sync(0xffffffffu, rowsum[a], off);

        __syncwarp();
        if (tx == 0) {
            #pragma unroll
            for (int a=0;a<4;a++) {
                s.M[ty*4+a] = m_new[a];
                s.L[ty*4+a] = s.L[ty*4+a]*scale[a] + rowsum[a];
            }
        }

        // rescale packed accumulators
        #pragma unroll
        for (int a=0;a<4;a++) {
            const u64 sc = pack2(scale[a], scale[a]);
            #pragma unroll
            for (int c=0;c<4;c++) o2[a][c] = mul2(o2[a][c], sc);
        }

        // stage P transposed [k][q]
        #pragma unroll
        for (int a=0;a<4;a++)
            #pragma unroll
            for (int c=0;c<4;c++)
                s.P[tx*4+c][ty*4+a] = p[a][c];
        __syncthreads();

        // --- O += P @ V, packed (or,oi) ---
        #pragma unroll 4
        for (int kk = 0; kk < 64; ++kk) {
            const float4 p4 = *(const float4*)&s.P[kk][ty*4];
            const ulonglong2 va = *(const ulonglong2*)&s.Vc[kk][tx*4];
            const ulonglong2 vb = *(const ulonglong2*)&s.Vc[kk][tx*4+2];
            const u64 vv[4] = {va.x, va.y, vb.x, vb.y};
            const u64 pp[4] = {pack2(p4.x,p4.x), pack2(p4.y,p4.y),
                               pack2(p4.z,p4.z), pack2(p4.w,p4.w)};
            #pragma unroll
            for (int a=0;a<4;a++)
                #pragma unroll
                for (int c=0;c<4;c++)
                    o2[a][c] = fma2(pp[a], vv[c], o2[a][c]);
        }
    }

    __syncthreads();
    float inv[4];
    #pragma unroll
    for (int a=0;a<4;a++) inv[a] = 1.f / s.L[ty*4+a];

    #pragma unroll
    for (int a=0;a<4;a++) {
        const size_t row = (size_t)(qbase + ty*4 + a);
        float4 vr, vi;
        float orv, oiv;
        unpack2(o2[a][0], orv, oiv); vr.x = orv*inv[a]; vi.x = oiv*inv[a];
        unpack2(o2[a][1], orv, oiv); vr.y = orv*inv[a]; vi.y = oiv*inv[a];
        unpack2(o2[a][2], orv, oiv); vr.z = orv*inv[a]; vi.z = oiv*inv[a];
        unpack2(o2[a][3], orv, oiv); vr.w = orv*inv[a]; vi.w = oiv*inv[a];
        *(float4*)&out[row*H_ + tx*4]                 = vr;   // out_real
        *(float4*)&out[(size_t)M_*H_ + row*H_ + tx*4] = vi;   // out_imag
    }
}

// ---------------------------------------------------------------------------
extern "C" void kernel_launch(void* const* d_in, const int* in_sizes, int n_in,
                              void* d_out, int out_size)
{
    const float* xr  = (const float*)d_in[0];
    const float* xi  = (const float*)d_in[1];
    const float* Wkr = (const float*)d_in[2];
    const float* Wki = (const float*)d_in[3];
    const float* Wqr = (const float*)d_in[4];
    const float* Wqi = (const float*)d_in[5];
    const float* Wvr = (const float*)d_in[6];
    const float* Wvi = (const float*)d_in[7];

    cudaFuncSetAttribute(attn_kernel,
                         cudaFuncAttributeMaxDynamicSharedMemorySize,
                         (int)sizeof(AttnSmem));

    proj_kernel<<<M_/64, 256>>>(xr, xi, Wkr, Wki, Wqr, Wqi, Wvr, Wvi);

    dim3 ag(T_/64, B_);
    attn_kernel<<<ag, 256, sizeof(AttnSmem)>>>((float*)d_out);
}

// round 6
// speedup vs baseline: 2.0355x; 2.0254x over previous
#include <cuda_runtime.h>
#include <math_constants.h>

#define B_ 8
#define T_ 2048
#define C_ 1024
#define H_ 64
#define M_ (B_*T_)

// Projected tensors in FULL fp32. K stored transposed [h][M].
__device__ float g_qr[M_*H_], g_qi[M_*H_];
__device__ float g_ktr[(size_t)H_*M_], g_kti[(size_t)H_*M_];
__device__ float g_vr[M_*H_], g_vi[M_*H_];

__device__ __forceinline__ float f2tf(float x) {
    unsigned u; asm("cvt.rna.tf32.f32 %0, %1;" : "=r"(u) : "f"(x));
    return __uint_as_float(u);
}
__device__ __forceinline__ void mma8(float* d, const unsigned* a, const unsigned* b) {
    asm volatile("mma.sync.aligned.m16n8k8.row.col.f32.tf32.tf32.f32 "
        "{%0,%1,%2,%3}, {%4,%5,%6,%7}, {%8,%9}, {%0,%1,%2,%3};"
        : "+f"(d[0]), "+f"(d[1]), "+f"(d[2]), "+f"(d[3])
        : "r"(a[0]), "r"(a[1]), "r"(a[2]), "r"(a[3]), "r"(b[0]), "r"(b[1]));
}

// ===========================================================================
// Projection with 3xTF32 split. CTA = 128 rows x 64 cols of one matrix.
// A smem [ri][part][128][36], B smem [Wri][part][32][72].
// ===========================================================================
#define PJ_FLOATS (18432 + 9216)

__global__ __launch_bounds__(256) void proj_kernel(
    const float* __restrict__ xr,  const float* __restrict__ xi,
    const float* __restrict__ Wkr, const float* __restrict__ Wki,
    const float* __restrict__ Wqr, const float* __restrict__ Wqi,
    const float* __restrict__ Wvr, const float* __restrict__ Wvi)
{
    extern __shared__ float sm[];
    float* As = sm;               // [ri*2+part][128][36] : 4*4608
    float* Bs = sm + 18432;       // [wri*2+part][32][72] : 4*2304

    const int tid  = threadIdx.x;
    const int lane = tid & 31;
    const int w    = tid >> 5;
    const int wm   = w >> 1;
    const int wn   = w & 1;
    const int g    = lane >> 2;
    const int kl   = lane & 3;

    const int rt  = blockIdx.x / 3;
    const int mat = blockIdx.x % 3;   // 0=K 1=Q 2=V
    const int m0  = rt * 128;

    const float* Wr_ = (mat==0)? Wkr : (mat==1)? Wqr : Wvr;
    const float* Wi_ = (mat==0)? Wki : (mat==1)? Wqi : Wvi;

    float dR[2][4][4], dI[2][4][4];
    #pragma unroll
    for (int mt=0; mt<2; ++mt)
        #pragma unroll
        for (int nt=0; nt<4; ++nt)
            #pragma unroll
            for (int r=0; r<4; ++r) { dR[mt][nt][r]=0.f; dI[mt][nt][r]=0.f; }

    const int a_ri = tid >> 7;               // 0=xr, 1=xi
    const int a_m  = tid & 127;
    const float* a_src = (a_ri ? xi : xr) + (size_t)(m0 + a_m)*C_;
    float* a_h = As + a_ri*9216 + a_m*36;
    float* a_l = a_h + 4608;
    const int b_k = tid >> 3;                // 0..31
    const int b_n = (tid & 7) * 4;

    for (int c0 = 0; c0 < C_; c0 += 32) {
        __syncthreads();
        #pragma unroll
        for (int j = 0; j < 8; ++j) {
            float4 v = *(const float4*)(a_src + c0 + j*4);
            float4 h, l;
            h.x=f2tf(v.x); l.x=f2tf(v.x-h.x);
            h.y=f2tf(v.y); l.y=f2tf(v.y-h.y);
            h.z=f2tf(v.z); l.z=f2tf(v.z-h.z);
            h.w=f2tf(v.w); l.w=f2tf(v.w-h.w);
            *(float4*)(a_h + j*4) = h;
            *(float4*)(a_l + j*4) = l;
        }
        #pragma unroll
        for (int p = 0; p < 2; ++p) {
            const int n = b_n + 32*p;
            float4 wr = *(const float4*)(Wr_ + (size_t)(c0 + b_k)*H_ + n);
            float4 wi = *(const float4*)(Wi_ + (size_t)(c0 + b_k)*H_ + n);
            float4 rh, rl, ih, il;
            rh.x=f2tf(wr.x); rl.x=f2tf(wr.x-rh.x);
            rh.y=f2tf(wr.y); rl.y=f2tf(wr.y-rh.y);
            rh.z=f2tf(wr.z); rl.z=f2tf(wr.z-rh.z);
            rh.w=f2tf(wr.w); rl.w=f2tf(wr.w-rh.w);
            ih.x=f2tf(wi.x); il.x=f2tf(wi.x-ih.x);
            ih.y=f2tf(wi.y); il.y=f2tf(wi.y-ih.y);
            ih.z=f2tf(wi.z); il.z=f2tf(wi.z-ih.z);
            ih.w=f2tf(wi.w); il.w=f2tf(wi.w-ih.w);
            *(float4*)(Bs +    0 + b_k*72 + n) = rh;
            *(float4*)(Bs + 2304 + b_k*72 + n) = rl;
            *(float4*)(Bs + 4608 + b_k*72 + n) = ih;
            *(float4*)(Bs + 6912 + b_k*72 + n) = il;
        }
        __syncthreads();

        #pragma unroll
        for (int ks = 0; ks < 4; ++ks) {
            const int kk = ks*8;
            unsigned arh[2][4], arl[2][4], aih[2][4], ail[2][4], nih[2][4], nil[2][4];
            #pragma unroll
            for (int mt = 0; mt < 2; ++mt) {
                const int mrow = wm*32 + mt*16 + g;
                #pragma unroll
                for (int q = 0; q < 4; ++q) {
                    const int rr = mrow + ((q & 1) ? 8 : 0);
                    const int cc = kk + kl + ((q >> 1) ? 4 : 0);
                    arh[mt][q]=__float_as_uint(As[        rr*36 + cc]);
                    arl[mt][q]=__float_as_uint(As[ 4608 + rr*36 + cc]);
                    aih[mt][q]=__float_as_uint(As[ 9216 + rr*36 + cc]);
                    ail[mt][q]=__float_as_uint(As[13824 + rr*36 + cc]);
                    nih[mt][q]=aih[mt][q] ^ 0x80000000u;
                    nil[mt][q]=ail[mt][q] ^ 0x80000000u;
                }
            }
            #pragma unroll
            for (int nt = 0; nt < 4; ++nt) {
                const int n0 = wn*32 + nt*8 + g;
                unsigned brh[2], brl[2], bih[2], bil[2];
                brh[0]=__float_as_uint(Bs[       (kk+kl  )*72 + n0]);
                brh[1]=__float_as_uint(Bs[       (kk+kl+4)*72 + n0]);
                brl[0]=__float_as_uint(Bs[2304 + (kk+kl  )*72 + n0]);
                brl[1]=__float_as_uint(Bs[2304 + (kk+kl+4)*72 + n0]);
                bih[0]=__float_as_uint(Bs[4608 + (kk+kl  )*72 + n0]);
                bih[1]=__float_as_uint(Bs[4608 + (kk+kl+4)*72 + n0]);
                bil[0]=__float_as_uint(Bs[6912 + (kk+kl  )*72 + n0]);
                bil[1]=__float_as_uint(Bs[6912 + (kk+kl+4)*72 + n0]);
                #pragma unroll
                for (int mt = 0; mt < 2; ++mt) {
                    // dR = xr@Wr - xi@Wi (3x split each)
                    mma8(dR[mt][nt], arh[mt], brh);
                    mma8(dR[mt][nt], arh[mt], brl);
                    mma8(dR[mt][nt], arl[mt], brh);
                    mma8(dR[mt][nt], nih[mt], bih);
                    mma8(dR[mt][nt], nih[mt], bil);
                    mma8(dR[mt][nt], nil[mt], bih);
                    // dI = xi@Wr + xr@Wi
                    mma8(dI[mt][nt], aih[mt], brh);
                    mma8(dI[mt][nt], aih[mt], brl);
                    mma8(dI[mt][nt], ail[mt], brh);
                    mma8(dI[mt][nt], arh[mt], bih);
                    mma8(dI[mt][nt], arh[mt], bil);
                    mma8(dI[mt][nt], arl[mt], bih);
                }
            }
        }
    }

    #pragma unroll
    for (int mt = 0; mt < 2; ++mt) {
        const int rA = m0 + wm*32 + mt*16 + g;
        const int rB = rA + 8;
        #pragma unroll
        for (int nt = 0; nt < 4; ++nt) {
            const int c0 = wn*32 + nt*8 + 2*kl;
            if (mat == 0) {                    // K transposed [h][M]
                g_ktr[(size_t)(c0  )*M_ + rA] = dR[mt][nt][0];
                g_ktr[(size_t)(c0+1)*M_ + rA] = dR[mt][nt][1];
                g_ktr[(size_t)(c0  )*M_ + rB] = dR[mt][nt][2];
                g_ktr[(size_t)(c0+1)*M_ + rB] = dR[mt][nt][3];
                g_kti[(size_t)(c0  )*M_ + rA] = dI[mt][nt][0];
                g_kti[(size_t)(c0+1)*M_ + rA] = dI[mt][nt][1];
                g_kti[(size_t)(c0  )*M_ + rB] = dI[mt][nt][2];
                g_kti[(size_t)(c0+1)*M_ + rB] = dI[mt][nt][3];
            } else if (mat == 1) {
                *(float2*)(g_qr + (size_t)rA*H_ + c0) = make_float2(dR[mt][nt][0], dR[mt][nt][1]);
                *(float2*)(g_qr + (size_t)rB*H_ + c0) = make_float2(dR[mt][nt][2], dR[mt][nt][3]);
                *(float2*)(g_qi + (size_t)rA*H_ + c0) = make_float2(dI[mt][nt][0], dI[mt][nt][1]);
                *(float2*)(g_qi + (size_t)rB*H_ + c0) = make_float2(dI[mt][nt][2], dI[mt][nt][3]);
            } else {
                *(float2*)(g_vr + (size_t)rA*H_ + c0) = make_float2(dR[mt][nt][0], dR[mt][nt][1]);
                *(float2*)(g_vr + (size_t)rB*H_ + c0) = make_float2(dR[mt][nt][2], dR[mt][nt][3]);
                *(float2*)(g_vi + (size_t)rA*H_ + c0) = make_float2(dI[mt][nt][0], dI[mt][nt][1]);
                *(float2*)(g_vi + (size_t)rB*H_ + c0) = make_float2(dI[mt][nt][2], dI[mt][nt][3]);
            }
        }
    }
}

// ===========================================================================
// Flash attention: QK^T with split q,k (3xTF32); PV with split P, tf32 V.
// ===========================================================================
#define AQH 0                   // [2][64][68] = 8704
#define AQL 8704                // 8704
#define AKH 17408               // [2][64][72] = 9216
#define AKL 26624               // 9216
#define AV  35840               // 9216
#define APH 45056               // [64][68] = 4352
#define APL 49408               // 4352
#define ARM 53760               // 128
#define ARS 53888               // 128
#define AM  54016               // 64
#define AL  54080               // 64
#define AT_FLOATS 54144

__global__ __launch_bounds__(256, 1) void attn_kernel(float* __restrict__ out)
{
    extern __shared__ float sm[];
    float* redm = sm + ARM;
    float* reds = sm + ARS;
    float* sM = sm + AM;
    float* sL = sm + AL;

    const int b    = blockIdx.y;
    const int qt   = (int)gridDim.x - 1 - (int)blockIdx.x;  // heavy first
    const int tid  = threadIdx.x;
    const int lane = tid & 31;
    const int w    = tid >> 5;
    const int wm   = w >> 1;
    const int wn   = w & 1;
    const int g    = lane >> 2;
    const int kl   = lane & 3;
    const int qbase = b*T_ + qt*64;
    const int lr0 = wm*16 + g, lr1 = lr0 + 8;

    {   // stage Q hi/lo
        const int m = tid >> 2;
        #pragma unroll
        for (int ri = 0; ri < 2; ++ri) {
            const float* src = (ri ? g_qi : g_qr) + (size_t)(qbase + m)*H_;
            float* dh = sm + AQH + ri*4352 + m*68;
            float* dl = sm + AQL + ri*4352 + m*68;
            #pragma unroll
            for (int j = 0; j < 4; ++j) {
                const int c = (tid & 3)*4 + 16*j;
                float4 v = *(const float4*)(src + c);
                float4 h, l;
                h.x=f2tf(v.x); l.x=f2tf(v.x-h.x);
                h.y=f2tf(v.y); l.y=f2tf(v.y-h.y);
                h.z=f2tf(v.z); l.z=f2tf(v.z-h.z);
                h.w=f2tf(v.w); l.w=f2tf(v.w-h.w);
                *(float4*)(dh + c) = h;
                *(float4*)(dl + c) = l;
            }
        }
    }
    if (tid < 64) { sM[tid] = -CUDART_INF_F; sL[tid] = 0.f; }

    float Or[4][4], Oi[4][4];
    #pragma unroll
    for (int nt=0;nt<4;nt++)
        #pragma unroll
        for (int r=0;r<4;r++) { Or[nt][r]=0.f; Oi[nt][r]=0.f; }

    for (int kt = 0; kt <= qt; ++kt) {
        __syncthreads();
        const int kbase = b*T_ + kt*64;
        {   // stage K hi/lo (from transposed) and V (tf32)
            const int rr = tid >> 2;
            #pragma unroll
            for (int ri = 0; ri < 2; ++ri) {
                const float* ksrc = (ri ? g_kti : g_ktr) + (size_t)rr*M_ + kbase;
                const float* vsrc = (ri ? g_vi  : g_vr ) + (size_t)(kbase + rr)*H_;
                float* kh = sm + AKH + ri*4608 + rr*72;
                float* klo= sm + AKL + ri*4608 + rr*72;
                float* vd = sm + AV  + ri*4608 + rr*72;
                #pragma unroll
                for (int j = 0; j < 4; ++j) {
                    const int c = (tid & 3)*4 + 16*j;
                    float4 v = *(const float4*)(ksrc + c);
                    float4 h, l;
                    h.x=f2tf(v.x); l.x=f2tf(v.x-h.x);
                    h.y=f2tf(v.y); l.y=f2tf(v.y-h.y);
                    h.z=f2tf(v.z); l.z=f2tf(v.z-h.z);
                    h.w=f2tf(v.w); l.w=f2tf(v.w-h.w);
                    *(float4*)(kh + c) = h;
                    *(float4*)(klo+ c) = l;
                    float4 vv = *(const float4*)(vsrc + c);
                    vv.x=f2tf(vv.x); vv.y=f2tf(vv.y); vv.z=f2tf(vv.z); vv.w=f2tf(vv.w);
                    *(float4*)(vd + c) = vv;
                }
            }
        }
        __syncthreads();

        // ---- scores: Sr = qr@kr + qi@ki ; Si = qi@kr - qr@ki (split 3x) ----
        float Sr[4][4], Si[4][4];
        #pragma unroll
        for (int nt=0;nt<4;nt++)
            #pragma unroll
            for (int r=0;r<4;r++) { Sr[nt][r]=0.f; Si[nt][r]=0.f; }

        #pragma unroll
        for (int ks = 0; ks < 8; ++ks) {
            const int kk = ks*8;
            const int m = wm*16 + g;
            unsigned qrh[4], qrl[4], qih[4], qil[4], nrh[4], nrl[4];
            #pragma unroll
            for (int q = 0; q < 4; ++q) {
                const int rr = m + ((q & 1) ? 8 : 0);
                const int cc = kk + kl + ((q >> 1) ? 4 : 0);
                qrh[q]=__float_as_uint(sm[AQH +        rr*68 + cc]);
                qrl[q]=__float_as_uint(sm[AQL +        rr*68 + cc]);
                qih[q]=__float_as_uint(sm[AQH + 4352 + rr*68 + cc]);
                qil[q]=__float_as_uint(sm[AQL + 4352 + rr*68 + cc]);
                nrh[q]=qrh[q] ^ 0x80000000u;
                nrl[q]=qrl[q] ^ 0x80000000u;
            }
            #pragma unroll
            for (int nt = 0; nt < 4; ++nt) {
                const int n0 = wn*32 + nt*8 + g;
                unsigned krh[2], krl[2], kih[2], kil[2];
                krh[0]=__float_as_uint(sm[AKH +        (kk+kl  )*72 + n0]);
                krh[1]=__float_as_uint(sm[AKH +        (kk+kl+4)*72 + n0]);
                krl[0]=__float_as_uint(sm[AKL +        (kk+kl  )*72 + n0]);
                krl[1]=__float_as_uint(sm[AKL +        (kk+kl+4)*72 + n0]);
                kih[0]=__float_as_uint(sm[AKH + 4608 + (kk+kl  )*72 + n0]);
                kih[1]=__float_as_uint(sm[AKH + 4608 + (kk+kl+4)*72 + n0]);
                kil[0]=__float_as_uint(sm[AKL + 4608 + (kk+kl  )*72 + n0]);
                kil[1]=__float_as_uint(sm[AKL + 4608 + (kk+kl+4)*72 + n0]);
                mma8(Sr[nt], qrh, krh);
                mma8(Sr[nt], qrh, krl);
                mma8(Sr[nt], qrl, krh);
                mma8(Sr[nt], qih, kih);
                mma8(Sr[nt], qih, kil);
                mma8(Sr[nt], qil, kih);
                mma8(Si[nt], qih, krh);
                mma8(Si[nt], qih, krl);
                mma8(Si[nt], qil, krh);
                mma8(Si[nt], nrh, kih);
                mma8(Si[nt], nrh, kil);
                mma8(Si[nt], nrl, kih);
            }
        }

        // ---- magnitude + causal mask (into Sr) + warp-partial row max ----
        float mx0 = -CUDART_INF_F, mx1 = -CUDART_INF_F;
        #pragma unroll
        for (int nt = 0; nt < 4; ++nt)
            #pragma unroll
            for (int r = 0; r < 4; ++r) {
                const float sr = Sr[nt][r], si = Si[nt][r];
                const float m2 = fmaf(sr, sr, fmaf(si, si, 1e-4f));
                float v = m2 * rsqrtf(m2) * 0.125f;
                const int colg = kt*64 + wn*32 + nt*8 + 2*kl + (r&1);
                const int rowg = qt*64 + ((r<2) ? lr0 : lr1);
                v = (colg <= rowg) ? v : -CUDART_INF_F;
                Sr[nt][r] = v;
                if (r < 2) mx0 = fmaxf(mx0, v); else mx1 = fmaxf(mx1, v);
            }
        mx0 = fmaxf(mx0, __shfl_xor_sync(~0u, mx0, 1));
        mx0 = fmaxf(mx0, __shfl_xor_sync(~0u, mx0, 2));
        mx1 = fmaxf(mx1, __shfl_xor_sync(~0u, mx1, 1));
        mx1 = fmaxf(mx1, __shfl_xor_sync(~0u, mx1, 2));
        if (kl == 0) { redm[wn*64 + lr0] = mx0; redm[wn*64 + lr1] = mx1; }
        __syncthreads();

        const float mo0 = sM[lr0], mo1 = sM[lr1];
        const float mn0 = fmaxf(mo0, fmaxf(redm[lr0], redm[64+lr0]));
        const float mn1 = fmaxf(mo1, fmaxf(redm[lr1], redm[64+lr1]));
        const float sc0 = __expf(mo0 - mn0);
        const float sc1 = __expf(mo1 - mn1);

        float s0 = 0.f, s1 = 0.f;
        #pragma unroll
        for (int nt = 0; nt < 4; ++nt)
            #pragma unroll
            for (int r = 0; r < 4; ++r) {
                const float e = __expf(Sr[nt][r] - ((r<2)? mn0 : mn1));
                if (r < 2) s0 += e; else s1 += e;
                const int lr = (r<2)? lr0 : lr1;
                const int cc = wn*32 + nt*8 + 2*kl + (r&1);
                const float ph = f2tf(e);
                sm[APH + lr*68 + cc] = ph;
                sm[APL + lr*68 + cc] = f2tf(e - ph);
            }
        s0 += __shfl_xor_sync(~0u, s0, 1);
        s0 += __shfl_xor_sync(~0u, s0, 2);
        s1 += __shfl_xor_sync(~0u, s1, 1);
        s1 += __shfl_xor_sync(~0u, s1, 2);
        if (kl == 0) { reds[wn*64 + lr0] = s0; reds[wn*64 + lr1] = s1; }

        // rescale O accumulators
        #pragma unroll
        for (int nt = 0; nt < 4; ++nt)
            #pragma unroll
            for (int r = 0; r < 4; ++r) {
                const float sc = (r<2)? sc0 : sc1;
                Or[nt][r] *= sc; Oi[nt][r] *= sc;
            }
        __syncthreads();

        if (wn == 0 && kl == 0) {
            sL[lr0] = sL[lr0]*sc0 + reds[lr0] + reds[64+lr0];
            sL[lr1] = sL[lr1]*sc1 + reds[lr1] + reds[64+lr1];
            sM[lr0] = mn0; sM[lr1] = mn1;
        }

        // ---- O += P @ V (P split, V tf32) ----
        #pragma unroll
        for (int ks = 0; ks < 8; ++ks) {
            const int kk = ks*8;
            const int m = wm*16 + g;
            unsigned aph[4], apl[4];
            #pragma unroll
            for (int q = 0; q < 4; ++q) {
                const int rr = m + ((q & 1) ? 8 : 0);
                const int cc = kk + kl + ((q >> 1) ? 4 : 0);
                aph[q]=__float_as_uint(sm[APH + rr*68 + cc]);
                apl[q]=__float_as_uint(sm[APL + rr*68 + cc]);
            }
            #pragma unroll
            for (int nt = 0; nt < 4; ++nt) {
                const int h0 = wn*32 + nt*8 + g;
                unsigned bvr[2], bvi[2];
                bvr[0]=__float_as_uint(sm[AV +        (kk+kl  )*72 + h0]);
                bvr[1]=__float_as_uint(sm[AV +        (kk+kl+4)*72 + h0]);
                bvi[0]=__float_as_uint(sm[AV + 4608 + (kk+kl  )*72 + h0]);
                bvi[1]=__float_as_uint(sm[AV + 4608 + (kk+kl+4)*72 + h0]);
                mma8(Or[nt], aph, bvr);
                mma8(Or[nt], apl, bvr);
                mma8(Oi[nt], aph, bvi);
                mma8(Oi[nt], apl, bvi);
            }
        }
    }

    __syncthreads();
    const float inv0 = 1.f / sL[lr0];
    const float inv1 = 1.f / sL[lr1];
    #pragma unroll
    for (int nt = 0; nt < 4; ++nt) {
        const int h0 = wn*32 + nt*8 + 2*kl;
        const size_t rA = (size_t)(qbase + lr0);
        const size_t rB = (size_t)(qbase + lr1);
        *(float2*)(out + rA*H_ + h0) = make_float2(Or[nt][0]*inv0, Or[nt][1]*inv0);
        *(float2*)(out + rB*H_ + h0) = make_float2(Or[nt][2]*inv1, Or[nt][3]*inv1);
        *(float2*)(out + (size_t)M_*H_ + rA*H_ + h0) = make_float2(Oi[nt][0]*inv0, Oi[nt][1]*inv0);
        *(float2*)(out + (size_t)M_*H_ + rB*H_ + h0) = make_float2(Oi[nt][2]*inv1, Oi[nt][3]*inv1);
    }
}

// ---------------------------------------------------------------------------
extern "C" void kernel_launch(void* const* d_in, const int* in_sizes, int n_in,
                              void* d_out, int out_size)
{
    const float* xr  = (const float*)d_in[0];
    const float* xi  = (const float*)d_in[1];
    const float* Wkr = (const float*)d_in[2];
    const float* Wki = (const float*)d_in[3];
    const float* Wqr = (const float*)d_in[4];
    const float* Wqi = (const float*)d_in[5];
    const float* Wvr = (const float*)d_in[6];
    const float* Wvi = (const float*)d_in[7];

    cudaFuncSetAttribute(proj_kernel,
        cudaFuncAttributeMaxDynamicSharedMemorySize, PJ_FLOATS*4);
    cudaFuncSetAttribute(attn_kernel,
        cudaFuncAttributeMaxDynamicSharedMemorySize, AT_FLOATS*4);

    proj_kernel<<<(M_/128)*3, 256, PJ_FLOATS*4>>>(xr, xi, Wkr, Wki, Wqr, Wqi, Wvr, Wvi);

    dim3 ag(T_/64, B_);
    attn_kernel<<<ag, 256, AT_FLOATS*4>>>((float*)d_out);
}

// round 7
// speedup vs baseline: 3.2096x; 1.5769x over previous
#include <cuda_runtime.h>
#include <cuda_bf16.h>
#include <math_constants.h>

#define B_ 8
#define T_ 2048
#define C_ 1024
#define H_ 64
#define M_ (B_*T_)

// Projected tensors, full fp32. Q,K natural [M][H]; V transposed [H][M].
__device__ float g_qr[M_*H_], g_qi[M_*H_];
__device__ float g_kr[M_*H_], g_ki[M_*H_];
__device__ float g_vtr[(size_t)H_*M_], g_vti[(size_t)H_*M_];

// pack two f32 into bf16x2 (first arg -> low half = even k element)
__device__ __forceinline__ unsigned pkbf2(float lo, float hi) {
    unsigned r; asm("cvt.rn.bf16x2.f32 %0, %1, %2;" : "=r"(r) : "f"(hi), "f"(lo));
    return r;
}
__device__ __forceinline__ void split1(float x, float& h, float& l) {
    h = __bfloat162float(__float2bfloat16(x));
    l = x - h;
}
// m16n8k16 row.col f32 += bf16 * bf16
__device__ __forceinline__ void mma16(float* d, const unsigned* a, const unsigned* b) {
    asm volatile("mma.sync.aligned.m16n8k16.row.col.f32.bf16.bf16.f32 "
        "{%0,%1,%2,%3}, {%4,%5,%6,%7}, {%8,%9}, {%0,%1,%2,%3};"
        : "+f"(d[0]), "+f"(d[1]), "+f"(d[2]), "+f"(d[3])
        : "r"(a[0]), "r"(a[1]), "r"(a[2]), "r"(a[3]), "r"(b[0]), "r"(b[1]));
}

// ===========================================================================
// Projection, bf16-split. CTA = 128 rows x 64 cols of ONE matrix (bid%3).
//   out_r = xr@Wr - xi@Wi ; out_i = xi@Wr + xr@Wi  (negate Wi B-frags by XOR)
// A smem: 4 blocks [xr_h, xr_l, xi_h, xi_l], each [128 rows][20 u32] (16+pad).
// B smem: 4 blocks [wr_h, wr_l, wi_h, wi_l], each [64 n][20 u32] (W^T).
// ===========================================================================
#define PJ_AB0 0
#define PJ_BB0 10240
#define PJ_U32 15360

__global__ __launch_bounds__(256, 2) void proj_kernel(
    const float* __restrict__ xr,  const float* __restrict__ xi,
    const float* __restrict__ Wkr, const float* __restrict__ Wki,
    const float* __restrict__ Wqr, const float* __restrict__ Wqi,
    const float* __restrict__ Wvr, const float* __restrict__ Wvi)
{
    extern __shared__ unsigned smu[];
    unsigned* As = smu + PJ_AB0;      // blocks of 2560
    unsigned* Bs = smu + PJ_BB0;      // blocks of 1280

    const int tid  = threadIdx.x;
    const int lane = tid & 31;
    const int w    = tid >> 5;
    const int wm   = w >> 1;
    const int wn   = w & 1;
    const int g    = lane >> 2;
    const int kl   = lane & 3;

    const int rt  = blockIdx.x / 3;
    const int mat = blockIdx.x % 3;   // 0=K 1=Q 2=V
    const int m0  = rt * 128;

    const float* Wr_ = (mat==0)? Wkr : (mat==1)? Wqr : Wvr;
    const float* Wi_ = (mat==0)? Wki : (mat==1)? Wqi : Wvi;

    float dR[2][4][4], dI[2][4][4];
    #pragma unroll
    for (int mt=0; mt<2; ++mt)
        #pragma unroll
        for (int nt=0; nt<4; ++nt)
            #pragma unroll
            for (int r=0; r<4; ++r) { dR[mt][nt][r]=0.f; dI[mt][nt][r]=0.f; }

    const int a_ri = tid >> 7;               // 0=xr, 1=xi
    const int a_m  = tid & 127;
    const float* a_src = (a_ri ? xi : xr) + (size_t)(m0 + a_m)*C_;
    unsigned* a_h = As + (a_ri*2    )*2560 + a_m*20;
    unsigned* a_l = As + (a_ri*2 + 1)*2560 + a_m*20;
    const int b_n  = tid & 63;
    const int b_kq = tid >> 6;               // 0..3

    for (int c0 = 0; c0 < C_; c0 += 32) {
        __syncthreads();
        #pragma unroll
        for (int j = 0; j < 8; ++j) {        // A: one x row, 32 floats
            float4 v = *(const float4*)(a_src + c0 + j*4);
            float h0,l0,h1,l1,h2,l2,h3,l3;
            split1(v.x,h0,l0); split1(v.y,h1,l1);
            split1(v.z,h2,l2); split1(v.w,h3,l3);
            a_h[j*2  ] = pkbf2(h0,h1);
            a_h[j*2+1] = pkbf2(h2,h3);
            a_l[j*2  ] = pkbf2(l0,l1);
            a_l[j*2+1] = pkbf2(l2,l3);
        }
        #pragma unroll
        for (int jj = 0; jj < 4; ++jj) {     // B: W^T staging
            const int k2 = jj*4 + b_kq;      // pair 0..15
            const size_t krow = (size_t)(c0 + 2*k2);
            float wr0 = Wr_[krow*H_ + b_n], wr1 = Wr_[(krow+1)*H_ + b_n];
            float wi0 = Wi_[krow*H_ + b_n], wi1 = Wi_[(krow+1)*H_ + b_n];
            float h0,l0,h1,l1,h2,l2,h3,l3;
            split1(wr0,h0,l0); split1(wr1,h1,l1);
            split1(wi0,h2,l2); split1(wi1,h3,l3);
            Bs[0*1280 + b_n*20 + k2] = pkbf2(h0,h1);
            Bs[1*1280 + b_n*20 + k2] = pkbf2(l0,l1);
            Bs[2*1280 + b_n*20 + k2] = pkbf2(h2,h3);
            Bs[3*1280 + b_n*20 + k2] = pkbf2(l2,l3);
        }
        __syncthreads();

        #pragma unroll
        for (int ks = 0; ks < 2; ++ks) {
            const int pb = ks*8;
            #pragma unroll
            for (int mt = 0; mt < 2; ++mt) {
                const int mrow = wm*32 + mt*16 + g;
                unsigned frh[4], frl[4], fih[4], fil[4];
                #pragma unroll
                for (int q = 0; q < 4; ++q) {
                    const int rr = mrow + ((q & 1) ? 8 : 0);
                    const int cc = pb + kl + ((q >> 1) ? 4 : 0);
                    frh[q] = As[0*2560 + rr*20 + cc];
                    frl[q] = As[1*2560 + rr*20 + cc];
                    fih[q] = As[2*2560 + rr*20 + cc];
                    fil[q] = As[3*2560 + rr*20 + cc];
                }
                #pragma unroll
                for (int nt = 0; nt < 4; ++nt) {
                    const int n0 = wn*32 + nt*8 + g;
                    unsigned brh[2], brl[2], bih[2], bil[2], nih[2], nil_[2];
                    brh[0]=Bs[0*1280 + n0*20 + pb+kl];
                    brh[1]=Bs[0*1280 + n0*20 + pb+kl+4];
                    brl[0]=Bs[1*1280 + n0*20 + pb+kl];
                    brl[1]=Bs[1*1280 + n0*20 + pb+kl+4];
                    bih[0]=Bs[2*1280 + n0*20 + pb+kl];
                    bih[1]=Bs[2*1280 + n0*20 + pb+kl+4];
                    bil[0]=Bs[3*1280 + n0*20 + pb+kl];
                    bil[1]=Bs[3*1280 + n0*20 + pb+kl+4];
                    nih[0]=bih[0]^0x80008000u; nih[1]=bih[1]^0x80008000u;
                    nil_[0]=bil[0]^0x80008000u; nil_[1]=bil[1]^0x80008000u;
                    // dR = xr@Wr - xi@Wi
                    mma16(dR[mt][nt], frh, brh);
                    mma16(dR[mt][nt], frh, brl);
                    mma16(dR[mt][nt], frl, brh);
                    mma16(dR[mt][nt], fih, nih);
                    mma16(dR[mt][nt], fih, nil_);
                    mma16(dR[mt][nt], fil, nih);
                    // dI = xi@Wr + xr@Wi
                    mma16(dI[mt][nt], fih, brh);
                    mma16(dI[mt][nt], fih, brl);
                    mma16(dI[mt][nt], fil, brh);
                    mma16(dI[mt][nt], frh, bih);
                    mma16(dI[mt][nt], frh, bil);
                    mma16(dI[mt][nt], frl, bih);
                }
            }
        }
    }

    #pragma unroll
    for (int mt = 0; mt < 2; ++mt) {
        const int rA = m0 + wm*32 + mt*16 + g;
        const int rB = rA + 8;
        #pragma unroll
        for (int nt = 0; nt < 4; ++nt) {
            const int c0 = wn*32 + nt*8 + 2*kl;
            if (mat == 0) {                    // K natural
                *(float2*)(g_kr + (size_t)rA*H_ + c0) = make_float2(dR[mt][nt][0], dR[mt][nt][1]);
                *(float2*)(g_kr + (size_t)rB*H_ + c0) = make_float2(dR[mt][nt][2], dR[mt][nt][3]);
                *(float2*)(g_ki + (size_t)rA*H_ + c0) = make_float2(dI[mt][nt][0], dI[mt][nt][1]);
                *(float2*)(g_ki + (size_t)rB*H_ + c0) = make_float2(dI[mt][nt][2], dI[mt][nt][3]);
            } else if (mat == 1) {             // Q natural
                *(float2*)(g_qr + (size_t)rA*H_ + c0) = make_float2(dR[mt][nt][0], dR[mt][nt][1]);
                *(float2*)(g_qr + (size_t)rB*H_ + c0) = make_float2(dR[mt][nt][2], dR[mt][nt][3]);
                *(float2*)(g_qi + (size_t)rA*H_ + c0) = make_float2(dI[mt][nt][0], dI[mt][nt][1]);
                *(float2*)(g_qi + (size_t)rB*H_ + c0) = make_float2(dI[mt][nt][2], dI[mt][nt][3]);
            } else {                           // V transposed [h][M]
                g_vtr[(size_t)(c0  )*M_ + rA] = dR[mt][nt][0];
                g_vtr[(size_t)(c0+1)*M_ + rA] = dR[mt][nt][1];
                g_vtr[(size_t)(c0  )*M_ + rB] = dR[mt][nt][2];
                g_vtr[(size_t)(c0+1)*M_ + rB] = dR[mt][nt][3];
                g_vti[(size_t)(c0  )*M_ + rA] = dI[mt][nt][0];
                g_vti[(size_t)(c0+1)*M_ + rA] = dI[mt][nt][1];
                g_vti[(size_t)(c0  )*M_ + rB] = dI[mt][nt][2];
                g_vti[(size_t)(c0+1)*M_ + rB] = dI[mt][nt][3];
            }
        }
    }
}

// ===========================================================================
// Flash attention, bf16-split m16n8k16.
// QH/QL: [ri][64 q][36 u32]; KH/KL: [ri][64 key][36]; VH/VL: [ri][64 h][36];
// PH/PL: [64 q][36]. All u32 = bf16 pair along k.
// ===========================================================================
#define AQH 0
#define AQL 4608
#define AKH 9216
#define AKL 13824
#define AVH 18432
#define AVL 23040
#define APH 27648
#define APL 29952
#define AT_U32 32256
#define AT_BYTES ((AT_U32 + 384)*4)

__global__ __launch_bounds__(256, 1) void attn_kernel(float* __restrict__ out)
{
    extern __shared__ unsigned smu[];
    float* fsm  = (float*)(smu + AT_U32);
    float* redm = fsm;          // [2][64]
    float* reds = fsm + 128;    // [2][64]
    float* sM   = fsm + 256;
    float* sL   = fsm + 320;

    const int b    = blockIdx.y;
    const int qt   = (int)gridDim.x - 1 - (int)blockIdx.x;  // heavy first
    const int tid  = threadIdx.x;
    const int lane = tid & 31;
    const int w    = tid >> 5;
    const int wm   = w >> 1;
    const int wn   = w & 1;
    const int g    = lane >> 2;
    const int kl   = lane & 3;
    const int qbase = b*T_ + qt*64;
    const int lr0 = wm*16 + g, lr1 = lr0 + 8;

    {   // stage Q hi/lo (bf16 split), row m = tid>>2
        const int m  = tid >> 2;
        const int qq = tid & 3;
        #pragma unroll
        for (int ri = 0; ri < 2; ++ri) {
            const float* src = (ri ? g_qi : g_qr) + (size_t)(qbase + m)*H_;
            #pragma unroll
            for (int j = 0; j < 4; ++j) {
                const int c = qq*16 + j*4;
                float4 v = *(const float4*)(src + c);
                float h0,l0,h1,l1,h2,l2,h3,l3;
                split1(v.x,h0,l0); split1(v.y,h1,l1);
                split1(v.z,h2,l2); split1(v.w,h3,l3);
                smu[AQH + ri*2304 + m*36 + c/2    ] = pkbf2(h0,h1);
                smu[AQH + ri*2304 + m*36 + c/2 + 1] = pkbf2(h2,h3);
                smu[AQL + ri*2304 + m*36 + c/2    ] = pkbf2(l0,l1);
                smu[AQL + ri*2304 + m*36 + c/2 + 1] = pkbf2(l2,l3);
            }
        }
    }
    if (tid < 64) { sM[tid] = -CUDART_INF_F; sL[tid] = 0.f; }

    float Or[4][4], Oi[4][4];
    #pragma unroll
    for (int nt=0;nt<4;nt++)
        #pragma unroll
        for (int r=0;r<4;r++) { Or[nt][r]=0.f; Oi[nt][r]=0.f; }

    for (int kt = 0; kt <= qt; ++kt) {
        __syncthreads();
        const int kbase = b*T_ + kt*64;
        {   // stage K (natural) and V (from transposed) hi/lo
            const int m  = tid >> 2;
            const int qq = tid & 3;
            #pragma unroll
            for (int ri = 0; ri < 2; ++ri) {
                const float* ksrc = (ri ? g_ki  : g_kr ) + (size_t)(kbase + m)*H_;
                const float* vsrc = (ri ? g_vti : g_vtr) + (size_t)m*M_ + kbase;
                #pragma unroll
                for (int j = 0; j < 4; ++j) {
                    const int c = qq*16 + j*4;
                    float4 v = *(const float4*)(ksrc + c);
                    float h0,l0,h1,l1,h2,l2,h3,l3;
                    split1(v.x,h0,l0); split1(v.y,h1,l1);
                    split1(v.z,h2,l2); split1(v.w,h3,l3);
                    smu[AKH + ri*2304 + m*36 + c/2    ] = pkbf2(h0,h1);
                    smu[AKH + ri*2304 + m*36 + c/2 + 1] = pkbf2(h2,h3);
                    smu[AKL + ri*2304 + m*36 + c/2    ] = pkbf2(l0,l1);
                    smu[AKL + ri*2304 + m*36 + c/2 + 1] = pkbf2(l2,l3);
                    float4 u = *(const float4*)(vsrc + c);
                    split1(u.x,h0,l0); split1(u.y,h1,l1);
                    split1(u.z,h2,l2); split1(u.w,h3,l3);
                    smu[AVH + ri*2304 + m*36 + c/2    ] = pkbf2(h0,h1);
                    smu[AVH + ri*2304 + m*36 + c/2 + 1] = pkbf2(h2,h3);
                    smu[AVL + ri*2304 + m*36 + c/2    ] = pkbf2(l0,l1);
                    smu[AVL + ri*2304 + m*36 + c/2 + 1] = pkbf2(l2,l3);
                }
            }
        }
        __syncthreads();

        // ---- scores: Sr = qr@kr + qi@ki ; Si = qi@kr - qr@ki ----
        float Sr[4][4], Si[4][4];
        #pragma unroll
        for (int nt=0;nt<4;nt++)
            #pragma unroll
            for (int r=0;r<4;r++) { Sr[nt][r]=0.f; Si[nt][r]=0.f; }

        #pragma unroll
        for (int ks = 0; ks < 4; ++ks) {
            const int pb = ks*8;
            const int m = wm*16 + g;
            unsigned qrh[4], qrl[4], qih[4], qil[4];
            #pragma unroll
            for (int q = 0; q < 4; ++q) {
                const int rr = m + ((q & 1) ? 8 : 0);
                const int cc = pb + kl + ((q >> 1) ? 4 : 0);
                qrh[q]=smu[AQH +        rr*36 + cc];
                qrl[q]=smu[AQL +        rr*36 + cc];
                qih[q]=smu[AQH + 2304 + rr*36 + cc];
                qil[q]=smu[AQL + 2304 + rr*36 + cc];
            }
            #pragma unroll
            for (int nt = 0; nt < 4; ++nt) {
                const int n0 = wn*32 + nt*8 + g;
                unsigned krh[2], krl[2], kih[2], kil[2], nih[2], nil_[2];
                krh[0]=smu[AKH +        n0*36 + pb+kl];
                krh[1]=smu[AKH +        n0*36 + pb+kl+4];
                krl[0]=smu[AKL +        n0*36 + pb+kl];
                krl[1]=smu[AKL +        n0*36 + pb+kl+4];
                kih[0]=smu[AKH + 2304 + n0*36 + pb+kl];
                kih[1]=smu[AKH + 2304 + n0*36 + pb+kl+4];
                kil[0]=smu[AKL + 2304 + n0*36 + pb+kl];
                kil[1]=smu[AKL + 2304 + n0*36 + pb+kl+4];
                nih[0]=kih[0]^0x80008000u; nih[1]=kih[1]^0x80008000u;
                nil_[0]=kil[0]^0x80008000u; nil_[1]=kil[1]^0x80008000u;
                mma16(Sr[nt], qrh, krh);
                mma16(Sr[nt], qrh, krl);
                mma16(Sr[nt], qrl, krh);
                mma16(Sr[nt], qih, kih);
                mma16(Sr[nt], qih, kil);
                mma16(Sr[nt], qil, kih);
                mma16(Si[nt], qih, krh);
                mma16(Si[nt], qih, krl);
                mma16(Si[nt], qil, krh);
                mma16(Si[nt], qrh, nih);
                mma16(Si[nt], qrh, nil_);
                mma16(Si[nt], qrl, nih);
            }
        }

        // ---- magnitude + causal mask (into Sr) + warp-partial row max ----
        float mx0 = -CUDART_INF_F, mx1 = -CUDART_INF_F;
        #pragma unroll
        for (int nt = 0; nt < 4; ++nt)
            #pragma unroll
            for (int r = 0; r < 4; ++r) {
                const float sr = Sr[nt][r], si = Si[nt][r];
                const float m2 = fmaf(sr, sr, fmaf(si, si, 1e-4f));
                float v = m2 * rsqrtf(m2) * 0.125f;
                const int colg = kt*64 + wn*32 + nt*8 + 2*kl + (r&1);
                const int rowg = qt*64 + ((r<2) ? lr0 : lr1);
                v = (colg <= rowg) ? v : -CUDART_INF_F;
                Sr[nt][r] = v;
                if (r < 2) mx0 = fmaxf(mx0, v); else mx1 = fmaxf(mx1, v);
            }
        mx0 = fmaxf(mx0, __shfl_xor_sync(~0u, mx0, 1));
        mx0 = fmaxf(mx0, __shfl_xor_sync(~0u, mx0, 2));
        mx1 = fmaxf(mx1, __shfl_xor_sync(~0u, mx1, 1));
        mx1 = fmaxf(mx1, __shfl_xor_sync(~0u, mx1, 2));
        if (kl == 0) { redm[wn*64 + lr0] = mx0; redm[wn*64 + lr1] = mx1; }
        __syncthreads();

        const float mo0 = sM[lr0], mo1 = sM[lr1];
        const float mn0 = fmaxf(mo0, fmaxf(redm[lr0], redm[64+lr0]));
        const float mn1 = fmaxf(mo1, fmaxf(redm[lr1], redm[64+lr1]));
        const float sc0 = __expf(mo0 - mn0);
        const float sc1 = __expf(mo1 - mn1);

        float s0 = 0.f, s1 = 0.f;
        #pragma unroll
        for (int nt = 0; nt < 4; ++nt) {
            const float e0 = __expf(Sr[nt][0] - mn0);
            const float e1 = __expf(Sr[nt][1] - mn0);
            const float e2 = __expf(Sr[nt][2] - mn1);
            const float e3 = __expf(Sr[nt][3] - mn1);
            s0 += e0 + e1; s1 += e2 + e3;
            const int pidx = wn*16 + nt*4 + kl;
            float h0,l0,h1,l1,h2,l2,h3,l3;
            split1(e0,h0,l0); split1(e1,h1,l1);
            split1(e2,h2,l2); split1(e3,h3,l3);
            smu[APH + lr0*36 + pidx] = pkbf2(h0,h1);
            smu[APL + lr0*36 + pidx] = pkbf2(l0,l1);
            smu[APH + lr1*36 + pidx] = pkbf2(h2,h3);
            smu[APL + lr1*36 + pidx] = pkbf2(l2,l3);
        }
        s0 += __shfl_xor_sync(~0u, s0, 1);
        s0 += __shfl_xor_sync(~0u, s0, 2);
        s1 += __shfl_xor_sync(~0u, s1, 1);
        s1 += __shfl_xor_sync(~0u, s1, 2);
        if (kl == 0) { reds[wn*64 + lr0] = s0; reds[wn*64 + lr1] = s1; }

        // rescale O accumulators
        #pragma unroll
        for (int nt = 0; nt < 4; ++nt)
            #pragma unroll
            for (int r = 0; r < 4; ++r) {
                const float sc = (r<2)? sc0 : sc1;
                Or[nt][r] *= sc; Oi[nt][r] *= sc;
            }
        __syncthreads();

        if (wn == 0 && kl == 0) {
            sL[lr0] = sL[lr0]*sc0 + reds[lr0] + reds[64+lr0];
            sL[lr1] = sL[lr1]*sc1 + reds[lr1] + reds[64+lr1];
            sM[lr0] = mn0; sM[lr1] = mn1;
        }

        // ---- O += P @ V (P split x V split, drop lo*lo) ----
        #pragma unroll
        for (int ks = 0; ks < 4; ++ks) {
            const int pb = ks*8;
            const int m = wm*16 + g;
            unsigned aph[4], apl[4];
            #pragma unroll
            for (int q = 0; q < 4; ++q) {
                const int rr = m + ((q & 1) ? 8 : 0);
                const int cc = pb + kl + ((q >> 1) ? 4 : 0);
                aph[q]=smu[APH + rr*36 + cc];
                apl[q]=smu[APL + rr*36 + cc];
            }
            #pragma unroll
            for (int nt = 0; nt < 4; ++nt) {
                const int n0 = wn*32 + nt*8 + g;
                unsigned bvh[2], bvl[2], bwh[2], bwl[2];
                bvh[0]=smu[AVH +        n0*36 + pb+kl];
                bvh[1]=smu[AVH +        n0*36 + pb+kl+4];
                bvl[0]=smu[AVL +        n0*36 + pb+kl];
                bvl[1]=smu[AVL +        n0*36 + pb+kl+4];
                bwh[0]=smu[AVH + 2304 + n0*36 + pb+kl];
                bwh[1]=smu[AVH + 2304 + n0*36 + pb+kl+4];
                bwl[0]=smu[AVL + 2304 + n0*36 + pb+kl];
                bwl[1]=smu[AVL + 2304 + n0*36 + pb+kl+4];
                mma16(Or[nt], aph, bvh);
                mma16(Or[nt], aph, bvl);
                mma16(Or[nt], apl, bvh);
                mma16(Oi[nt], aph, bwh);
                mma16(Oi[nt], aph, bwl);
                mma16(Oi[nt], apl, bwh);
            }
        }
    }

    __syncthreads();
    const float inv0 = 1.f / sL[lr0];
    const float inv1 = 1.f / sL[lr1];
    #pragma unroll
    for (int nt = 0; nt < 4; ++nt) {
        const int h0 = wn*32 + nt*8 + 2*kl;
        const size_t rA = (size_t)(qbase + lr0);
        const size_t rB = (size_t)(qbase + lr1);
        *(float2*)(out + rA*H_ + h0) = make_float2(Or[nt][0]*inv0, Or[nt][1]*inv0);
        *(float2*)(out + rB*H_ + h0) = make_float2(Or[nt][2]*inv1, Or[nt][3]*inv1);
        *(float2*)(out + (size_t)M_*H_ + rA*H_ + h0) = make_float2(Oi[nt][0]*inv0, Oi[nt][1]*inv0);
        *(float2*)(out + (size_t)M_*H_ + rB*H_ + h0) = make_float2(Oi[nt][2]*inv1, Oi[nt][3]*inv1);
    }
}

// ---------------------------------------------------------------------------
extern "C" void kernel_launch(void* const* d_in, const int* in_sizes, int n_in,
                              void* d_out, int out_size)
{
    const float* xr  = (const float*)d_in[0];
    const float* xi  = (const float*)d_in[1];
    const float* Wkr = (const float*)d_in[2];
    const float* Wki = (const float*)d_in[3];
    const float* Wqr = (const float*)d_in[4];
    const float* Wqi = (const float*)d_in[5];
    const float* Wvr = (const float*)d_in[6];
    const float* Wvi = (const float*)d_in[7];

    cudaFuncSetAttribute(proj_kernel,
        cudaFuncAttributeMaxDynamicSharedMemorySize, PJ_U32*4);
    cudaFuncSetAttribute(attn_kernel,
        cudaFuncAttributeMaxDynamicSharedMemorySize, AT_BYTES);

    proj_kernel<<<(M_/128)*3, 256, PJ_U32*4>>>(xr, xi, Wkr, Wki, Wqr, Wqi, Wvr, Wvi);

    dim3 ag(T_/64, B_);
    attn_kernel<<<ag, 256, AT_BYTES>>>((float*)d_out);
}

// round 8
// speedup vs baseline: 3.3456x; 1.0424x over previous
#include <cuda_runtime.h>
#include <cuda_bf16.h>
#include <math_constants.h>

#define B_ 8
#define T_ 2048
#define C_ 1024
#define H_ 64
#define M_ (B_*T_)

// Packed bf16 hi/lo pairs (u32 = two bf16 along the mma k-dim).
// Q,K: [M][32] pairs along h.  V: transposed [H][M/2] pairs along key index.
__device__ unsigned g_qrh[M_*32], g_qrl[M_*32], g_qih[M_*32], g_qil[M_*32];
__device__ unsigned g_krh[M_*32], g_krl[M_*32], g_kih[M_*32], g_kil[M_*32];
__device__ unsigned g_vrh[(size_t)H_*(M_/2)], g_vrl[(size_t)H_*(M_/2)];
__device__ unsigned g_vih[(size_t)H_*(M_/2)], g_vil[(size_t)H_*(M_/2)];

__device__ __forceinline__ unsigned pkbf2(float lo, float hi) {
    unsigned r; asm("cvt.rn.bf16x2.f32 %0, %1, %2;" : "=r"(r) : "f"(hi), "f"(lo));
    return r;
}
__device__ __forceinline__ void split1(float x, float& h, float& l) {
    h = __bfloat162float(__float2bfloat16(x));
    l = x - h;
}
__device__ __forceinline__ void mma16(float* d, const unsigned* a, const unsigned* b) {
    asm volatile("mma.sync.aligned.m16n8k16.row.col.f32.bf16.bf16.f32 "
        "{%0,%1,%2,%3}, {%4,%5,%6,%7}, {%8,%9}, {%0,%1,%2,%3};"
        : "+f"(d[0]), "+f"(d[1]), "+f"(d[2]), "+f"(d[3])
        : "r"(a[0]), "r"(a[1]), "r"(a[2]), "r"(a[3]), "r"(b[0]), "r"(b[1]));
}

// ===========================================================================
// Projection, bf16-split mma. CTA = 128 rows x 64 cols of ONE matrix.
// Epilogue pre-packs outputs as bf16 hi/lo u32 pairs for the attention kernel.
// ===========================================================================
#define PJ_AB0 0
#define PJ_BB0 10240
#define PJ_U32 15360

__global__ __launch_bounds__(256, 2) void proj_kernel(
    const float* __restrict__ xr,  const float* __restrict__ xi,
    const float* __restrict__ Wkr, const float* __restrict__ Wki,
    const float* __restrict__ Wqr, const float* __restrict__ Wqi,
    const float* __restrict__ Wvr, const float* __restrict__ Wvi)
{
    extern __shared__ unsigned smu[];
    unsigned* As = smu + PJ_AB0;      // 4 blocks of 2560: xr_h, xr_l, xi_h, xi_l
    unsigned* Bs = smu + PJ_BB0;      // 4 blocks of 1280: wr_h, wr_l, wi_h, wi_l

    const int tid  = threadIdx.x;
    const int lane = tid & 31;
    const int w    = tid >> 5;
    const int wm   = w >> 1;
    const int wn   = w & 1;
    const int g    = lane >> 2;
    const int kl   = lane & 3;

    const int rt  = blockIdx.x / 3;
    const int mat = blockIdx.x % 3;   // 0=K 1=Q 2=V
    const int m0  = rt * 128;

    const float* Wr_ = (mat==0)? Wkr : (mat==1)? Wqr : Wvr;
    const float* Wi_ = (mat==0)? Wki : (mat==1)? Wqi : Wvi;

    float dR[2][4][4], dI[2][4][4];
    #pragma unroll
    for (int mt=0; mt<2; ++mt)
        #pragma unroll
        for (int nt=0; nt<4; ++nt)
            #pragma unroll
            for (int r=0; r<4; ++r) { dR[mt][nt][r]=0.f; dI[mt][nt][r]=0.f; }

    const int a_ri = tid >> 7;
    const int a_m  = tid & 127;
    const float* a_src = (a_ri ? xi : xr) + (size_t)(m0 + a_m)*C_;
    unsigned* a_h = As + (a_ri*2    )*2560 + a_m*20;
    unsigned* a_l = As + (a_ri*2 + 1)*2560 + a_m*20;
    const int b_n  = tid & 63;
    const int b_kq = tid >> 6;

    for (int c0 = 0; c0 < C_; c0 += 32) {
        __syncthreads();
        #pragma unroll
        for (int j = 0; j < 8; ++j) {
            float4 v = *(const float4*)(a_src + c0 + j*4);
            float h0,l0,h1,l1,h2,l2,h3,l3;
            split1(v.x,h0,l0); split1(v.y,h1,l1);
            split1(v.z,h2,l2); split1(v.w,h3,l3);
            a_h[j*2  ] = pkbf2(h0,h1);
            a_h[j*2+1] = pkbf2(h2,h3);
            a_l[j*2  ] = pkbf2(l0,l1);
            a_l[j*2+1] = pkbf2(l2,l3);
        }
        #pragma unroll
        for (int jj = 0; jj < 4; ++jj) {
            const int k2 = jj*4 + b_kq;
            const size_t krow = (size_t)(c0 + 2*k2);
            float wr0 = Wr_[krow*H_ + b_n], wr1 = Wr_[(krow+1)*H_ + b_n];
            float wi0 = Wi_[krow*H_ + b_n], wi1 = Wi_[(krow+1)*H_ + b_n];
            float h0,l0,h1,l1,h2,l2,h3,l3;
            split1(wr0,h0,l0); split1(wr1,h1,l1);
            split1(wi0,h2,l2); split1(wi1,h3,l3);
            Bs[0*1280 + b_n*20 + k2] = pkbf2(h0,h1);
            Bs[1*1280 + b_n*20 + k2] = pkbf2(l0,l1);
            Bs[2*1280 + b_n*20 + k2] = pkbf2(h2,h3);
            Bs[3*1280 + b_n*20 + k2] = pkbf2(l2,l3);
        }
        __syncthreads();

        #pragma unroll
        for (int ks = 0; ks < 2; ++ks) {
            const int pb = ks*8;
            #pragma unroll
            for (int mt = 0; mt < 2; ++mt) {
                const int mrow = wm*32 + mt*16 + g;
                unsigned frh[4], frl[4], fih[4], fil[4];
                #pragma unroll
                for (int q = 0; q < 4; ++q) {
                    const int rr = mrow + ((q & 1) ? 8 : 0);
                    const int cc = pb + kl + ((q >> 1) ? 4 : 0);
                    frh[q] = As[0*2560 + rr*20 + cc];
                    frl[q] = As[1*2560 + rr*20 + cc];
                    fih[q] = As[2*2560 + rr*20 + cc];
                    fil[q] = As[3*2560 + rr*20 + cc];
                }
                #pragma unroll
                for (int nt = 0; nt < 4; ++nt) {
                    const int n0 = wn*32 + nt*8 + g;
                    unsigned brh[2], brl[2], bih[2], bil[2], nih[2], nil_[2];
                    brh[0]=Bs[0*1280 + n0*20 + pb+kl];
                    brh[1]=Bs[0*1280 + n0*20 + pb+kl+4];
                    brl[0]=Bs[1*1280 + n0*20 + pb+kl];
                    brl[1]=Bs[1*1280 + n0*20 + pb+kl+4];
                    bih[0]=Bs[2*1280 + n0*20 + pb+kl];
                    bih[1]=Bs[2*1280 + n0*20 + pb+kl+4];
                    bil[0]=Bs[3*1280 + n0*20 + pb+kl];
                    bil[1]=Bs[3*1280 + n0*20 + pb+kl+4];
                    nih[0]=bih[0]^0x80008000u; nih[1]=bih[1]^0x80008000u;
                    nil_[0]=bil[0]^0x80008000u; nil_[1]=bil[1]^0x80008000u;
                    mma16(dR[mt][nt], frh, brh);
                    mma16(dR[mt][nt], frh, brl);
                    mma16(dR[mt][nt], frl, brh);
                    mma16(dR[mt][nt], fih, nih);
                    mma16(dR[mt][nt], fih, nil_);
                    mma16(dR[mt][nt], fil, nih);
                    mma16(dI[mt][nt], fih, brh);
                    mma16(dI[mt][nt], fih, brl);
                    mma16(dI[mt][nt], fil, brh);
                    mma16(dI[mt][nt], frh, bih);
                    mma16(dI[mt][nt], frh, bil);
                    mma16(dI[mt][nt], frl, bih);
                }
            }
        }
    }

    // ---- epilogue: split + pack ----
    if (mat != 2) {
        unsigned *QRh, *QRl, *QIh, *QIl;
        if (mat == 0) { QRh=g_krh; QRl=g_krl; QIh=g_kih; QIl=g_kil; }
        else          { QRh=g_qrh; QRl=g_qrl; QIh=g_qih; QIl=g_qil; }
        #pragma unroll
        for (int mt = 0; mt < 2; ++mt) {
            const int rA = m0 + wm*32 + mt*16 + g;
            const int rB = rA + 8;
            #pragma unroll
            for (int nt = 0; nt < 4; ++nt) {
                const int pidx = wn*16 + nt*4 + kl;   // pair index along h
                float h0,l0,h1,l1;
                split1(dR[mt][nt][0],h0,l0); split1(dR[mt][nt][1],h1,l1);
                QRh[(size_t)rA*32 + pidx] = pkbf2(h0,h1);
                QRl[(size_t)rA*32 + pidx] = pkbf2(l0,l1);
                split1(dR[mt][nt][2],h0,l0); split1(dR[mt][nt][3],h1,l1);
                QRh[(size_t)rB*32 + pidx] = pkbf2(h0,h1);
                QRl[(size_t)rB*32 + pidx] = pkbf2(l0,l1);
                split1(dI[mt][nt][0],h0,l0); split1(dI[mt][nt][1],h1,l1);
                QIh[(size_t)rA*32 + pidx] = pkbf2(h0,h1);
                QIl[(size_t)rA*32 + pidx] = pkbf2(l0,l1);
                split1(dI[mt][nt][2],h0,l0); split1(dI[mt][nt][3],h1,l1);
                QIh[(size_t)rB*32 + pidx] = pkbf2(h0,h1);
                QIl[(size_t)rB*32 + pidx] = pkbf2(l0,l1);
            }
        }
    } else {
        // V: transposed [h][M/2], pairs along M. Row-pair exchange via shfl.
        #pragma unroll
        for (int mt = 0; mt < 2; ++mt) {
            const int rA = m0 + wm*32 + mt*16 + g;    // parity(rA) == parity(g)
            const int rB = rA + 8;
            #pragma unroll
            for (int nt = 0; nt < 4; ++nt) {
                const int c0 = wn*32 + nt*8 + 2*kl;
                float pr[4], pi[4];
                #pragma unroll
                for (int r=0;r<4;++r) {
                    pr[r] = __shfl_xor_sync(~0u, dR[mt][nt][r], 4);
                    pi[r] = __shfl_xor_sync(~0u, dI[mt][nt][r], 4);
                }
                if ((g & 1) == 0) {
                    const size_t pA = (size_t)(rA >> 1);
                    const size_t pB = (size_t)(rB >> 1);
                    float h0,l0,h1,l1;
                    split1(dR[mt][nt][0],h0,l0); split1(pr[0],h1,l1);
                    g_vrh[(size_t)c0*(M_/2) + pA] = pkbf2(h0,h1);
                    g_vrl[(size_t)c0*(M_/2) + pA] = pkbf2(l0,l1);
                    split1(dR[mt][nt][1],h0,l0); split1(pr[1],h1,l1);
                    g_vrh[(size_t)(c0+1)*(M_/2) + pA] = pkbf2(h0,h1);
                    g_vrl[(size_t)(c0+1)*(M_/2) + pA] = pkbf2(l0,l1);
                    split1(dR[mt][nt][2],h0,l0); split1(pr[2],h1,l1);
                    g_vrh[(size_t)c0*(M_/2) + pB] = pkbf2(h0,h1);
                    g_vrl[(size_t)c0*(M_/2) + pB] = pkbf2(l0,l1);
                    split1(dR[mt][nt][3],h0,l0); split1(pr[3],h1,l1);
                    g_vrh[(size_t)(c0+1)*(M_/2) + pB] = pkbf2(h0,h1);
                    g_vrl[(size_t)(c0+1)*(M_/2) + pB] = pkbf2(l0,l1);
                    split1(dI[mt][nt][0],h0,l0); split1(pi[0],h1,l1);
                    g_vih[(size_t)c0*(M_/2) + pA] = pkbf2(h0,h1);
                    g_vil[(size_t)c0*(M_/2) + pA] = pkbf2(l0,l1);
                    split1(dI[mt][nt][1],h0,l0); split1(pi[1],h1,l1);
                    g_vih[(size_t)(c0+1)*(M_/2) + pA] = pkbf2(h0,h1);
                    g_vil[(size_t)(c0+1)*(M_/2) + pA] = pkbf2(l0,l1);
                    split1(dI[mt][nt][2],h0,l0); split1(pi[2],h1,l1);
                    g_vih[(size_t)c0*(M_/2) + pB] = pkbf2(h0,h1);
                    g_vil[(size_t)c0*(M_/2) + pB] = pkbf2(l0,l1);
                    split1(dI[mt][nt][3],h0,l0); split1(pi[3],h1,l1);
                    g_vih[(size_t)(c0+1)*(M_/2) + pB] = pkbf2(h0,h1);
                    g_vil[(size_t)(c0+1)*(M_/2) + pB] = pkbf2(l0,l1);
                }
            }
        }
    }
}

// ===========================================================================
// Flash attention, 512 threads, 4x4 warp grid (warp = 16 q x 16 cols).
// Staging is pure u32 copy from pre-packed gmem.
// ===========================================================================
#define AQH 0
#define AQL 4608
#define AKH 9216
#define AKL 13824
#define AVH 18432
#define AVL 23040
#define APH 27648
#define APL 29952
#define AT_U32 32256
#define AT_BYTES ((AT_U32 + 640)*4)

__global__ __launch_bounds__(512, 1) void attn_kernel(float* __restrict__ out)
{
    extern __shared__ unsigned smu[];
    float* fsm  = (float*)(smu + AT_U32);
    float* redm = fsm;          // [4][64]
    float* reds = fsm + 256;    // [4][64]
    float* sM   = fsm + 512;
    float* sL   = fsm + 576;

    const int b    = blockIdx.y;
    const int qt   = (int)gridDim.x - 1 - (int)blockIdx.x;  // heavy first
    const int tid  = threadIdx.x;
    const int lane = tid & 31;
    const int w    = tid >> 5;
    const int wm   = w >> 2;     // 0..3 : 16 q-rows
    const int wn   = w & 3;      // 0..3 : 16 cols
    const int g    = lane >> 2;
    const int kl   = lane & 3;
    const int qbase = b*T_ + qt*64;
    const int lr0 = wm*16 + g, lr1 = lr0 + 8;

    {   // stage Q (pure copy)
        const int m  = tid >> 3;
        const int qq = (tid & 7)*4;
        const size_t base = (size_t)(qbase + m)*32 + qq;
        *(uint4*)&smu[AQH +        m*36 + qq] = *(const uint4*)&g_qrh[base];
        *(uint4*)&smu[AQH + 2304 + m*36 + qq] = *(const uint4*)&g_qih[base];
        *(uint4*)&smu[AQL +        m*36 + qq] = *(const uint4*)&g_qrl[base];
        *(uint4*)&smu[AQL + 2304 + m*36 + qq] = *(const uint4*)&g_qil[base];
    }
    if (tid < 64) { sM[tid] = -CUDART_INF_F; sL[tid] = 0.f; }

    float Or[2][4], Oi[2][4];
    #pragma unroll
    for (int nt=0;nt<2;nt++)
        #pragma unroll
        for (int r=0;r<4;r++) { Or[nt][r]=0.f; Oi[nt][r]=0.f; }

    for (int kt = 0; kt <= qt; ++kt) {
        __syncthreads();
        const int kbase = b*T_ + kt*64;
        {   // stage K and V (pure copy)
            const int m  = tid >> 3;
            const int qq = (tid & 7)*4;
            const size_t kb = (size_t)(kbase + m)*32 + qq;
            *(uint4*)&smu[AKH +        m*36 + qq] = *(const uint4*)&g_krh[kb];
            *(uint4*)&smu[AKH + 2304 + m*36 + qq] = *(const uint4*)&g_kih[kb];
            *(uint4*)&smu[AKL +        m*36 + qq] = *(const uint4*)&g_krl[kb];
            *(uint4*)&smu[AKL + 2304 + m*36 + qq] = *(const uint4*)&g_kil[kb];
            const size_t vb = (size_t)m*(M_/2) + (size_t)(kbase >> 1) + qq;
            *(uint4*)&smu[AVH +        m*36 + qq] = *(const uint4*)&g_vrh[vb];
            *(uint4*)&smu[AVH + 2304 + m*36 + qq] = *(const uint4*)&g_vih[vb];
            *(uint4*)&smu[AVL +        m*36 + qq] = *(const uint4*)&g_vrl[vb];
            *(uint4*)&smu[AVL + 2304 + m*36 + qq] = *(const uint4*)&g_vil[vb];
        }
        __syncthreads();

        // ---- scores ----
        float Sr[2][4], Si[2][4];
        #pragma unroll
        for (int nt=0;nt<2;nt++)
            #pragma unroll
            for (int r=0;r<4;r++) { Sr[nt][r]=0.f; Si[nt][r]=0.f; }

        #pragma unroll
        for (int ks = 0; ks < 4; ++ks) {
            const int pb = ks*8;
            const int m = wm*16 + g;
            unsigned qrh[4], qrl[4], qih[4], qil[4];
            #pragma unroll
            for (int q = 0; q < 4; ++q) {
                const int rr = m + ((q & 1) ? 8 : 0);
                const int cc = pb + kl + ((q >> 1) ? 4 : 0);
                qrh[q]=smu[AQH +        rr*36 + cc];
                qrl[q]=smu[AQL +        rr*36 + cc];
                qih[q]=smu[AQH + 2304 + rr*36 + cc];
                qil[q]=smu[AQL + 2304 + rr*36 + cc];
            }
            #pragma unroll
            for (int nt = 0; nt < 2; ++nt) {
                const int n0 = wn*16 + nt*8 + g;
                unsigned krh[2], krl[2], kih[2], kil[2], nih[2], nil_[2];
                krh[0]=smu[AKH +        n0*36 + pb+kl];
                krh[1]=smu[AKH +        n0*36 + pb+kl+4];
                krl[0]=smu[AKL +        n0*36 + pb+kl];
                krl[1]=smu[AKL +        n0*36 + pb+kl+4];
                kih[0]=smu[AKH + 2304 + n0*36 + pb+kl];
                kih[1]=smu[AKH + 2304 + n0*36 + pb+kl+4];
                kil[0]=smu[AKL + 2304 + n0*36 + pb+kl];
                kil[1]=smu[AKL + 2304 + n0*36 + pb+kl+4];
                nih[0]=kih[0]^0x80008000u; nih[1]=kih[1]^0x80008000u;
                nil_[0]=kil[0]^0x80008000u; nil_[1]=kil[1]^0x80008000u;
                mma16(Sr[nt], qrh, krh);
                mma16(Sr[nt], qrh, krl);
                mma16(Sr[nt], qrl, krh);
                mma16(Sr[nt], qih, kih);
                mma16(Sr[nt], qih, kil);
                mma16(Sr[nt], qil, kih);
                mma16(Si[nt], qih, krh);
                mma16(Si[nt], qih, krl);
                mma16(Si[nt], qil, krh);
                mma16(Si[nt], qrh, nih);
                mma16(Si[nt], qrh, nil_);
                mma16(Si[nt], qrl, nih);
            }
        }

        // ---- magnitude + causal mask + partial row max ----
        float mx0 = -CUDART_INF_F, mx1 = -CUDART_INF_F;
        #pragma unroll
        for (int nt = 0; nt < 2; ++nt)
            #pragma unroll
            for (int r = 0; r < 4; ++r) {
                const float sr = Sr[nt][r], si = Si[nt][r];
                const float m2 = fmaf(sr, sr, fmaf(si, si, 1e-4f));
                float v = m2 * rsqrtf(m2) * 0.125f;
                const int colg = kt*64 + wn*16 + nt*8 + 2*kl + (r&1);
                const int rowg = qt*64 + ((r<2) ? lr0 : lr1);
                v = (colg <= rowg) ? v : -CUDART_INF_F;
                Sr[nt][r] = v;
                if (r < 2) mx0 = fmaxf(mx0, v); else mx1 = fmaxf(mx1, v);
            }
        mx0 = fmaxf(mx0, __shfl_xor_sync(~0u, mx0, 1));
        mx0 = fmaxf(mx0, __shfl_xor_sync(~0u, mx0, 2));
        mx1 = fmaxf(mx1, __shfl_xor_sync(~0u, mx1, 1));
        mx1 = fmaxf(mx1, __shfl_xor_sync(~0u, mx1, 2));
        if (kl == 0) { redm[wn*64 + lr0] = mx0; redm[wn*64 + lr1] = mx1; }
        __syncthreads();

        const float mo0 = sM[lr0], mo1 = sM[lr1];
        const float mn0 = fmaxf(mo0, fmaxf(fmaxf(redm[lr0], redm[64+lr0]),
                                           fmaxf(redm[128+lr0], redm[192+lr0])));
        const float mn1 = fmaxf(mo1, fmaxf(fmaxf(redm[lr1], redm[64+lr1]),
                                           fmaxf(redm[128+lr1], redm[192+lr1])));
        const float sc0 = __expf(mo0 - mn0);
        const float sc1 = __expf(mo1 - mn1);

        float s0 = 0.f, s1 = 0.f;
        #pragma unroll
        for (int nt = 0; nt < 2; ++nt) {
            const float e0 = __expf(Sr[nt][0] - mn0);
            const float e1 = __expf(Sr[nt][1] - mn0);
            const float e2 = __expf(Sr[nt][2] - mn1);
            const float e3 = __expf(Sr[nt][3] - mn1);
            s0 += e0 + e1; s1 += e2 + e3;
            const int pidx = wn*8 + nt*4 + kl;
            float h0,l0,h1,l1,h2,l2,h3,l3;
            split1(e0,h0,l0); split1(e1,h1,l1);
            split1(e2,h2,l2); split1(e3,h3,l3);
            smu[APH + lr0*36 + pidx] = pkbf2(h0,h1);
            smu[APL + lr0*36 + pidx] = pkbf2(l0,l1);
            smu[APH + lr1*36 + pidx] = pkbf2(h2,h3);
            smu[APL + lr1*36 + pidx] = pkbf2(l2,l3);
        }
        s0 += __shfl_xor_sync(~0u, s0, 1);
        s0 += __shfl_xor_sync(~0u, s0, 2);
        s1 += __shfl_xor_sync(~0u, s1, 1);
        s1 += __shfl_xor_sync(~0u, s1, 2);
        if (kl == 0) { reds[wn*64 + lr0] = s0; reds[wn*64 + lr1] = s1; }

        #pragma unroll
        for (int nt = 0; nt < 2; ++nt)
            #pragma unroll
            for (int r = 0; r < 4; ++r) {
                const float sc = (r<2)? sc0 : sc1;
                Or[nt][r] *= sc; Oi[nt][r] *= sc;
            }
        __syncthreads();

        if (wn == 0 && kl == 0) {
            sL[lr0] = sL[lr0]*sc0 + reds[lr0] + reds[64+lr0] + reds[128+lr0] + reds[192+lr0];
            sL[lr1] = sL[lr1]*sc1 + reds[lr1] + reds[64+lr1] + reds[128+lr1] + reds[192+lr1];
            sM[lr0] = mn0; sM[lr1] = mn1;
        }

        // ---- O += P @ V ----
        #pragma unroll
        for (int ks = 0; ks < 4; ++ks) {
            const int pb = ks*8;
            const int m = wm*16 + g;
            unsigned aph[4], apl[4];
            #pragma unroll
            for (int q = 0; q < 4; ++q) {
                const int rr = m + ((q & 1) ? 8 : 0);
                const int cc = pb + kl + ((q >> 1) ? 4 : 0);
                aph[q]=smu[APH + rr*36 + cc];
                apl[q]=smu[APL + rr*36 + cc];
            }
            #pragma unroll
            for (int nt = 0; nt < 2; ++nt) {
                const int n0 = wn*16 + nt*8 + g;
                unsigned bvh[2], bvl[2], bwh[2], bwl[2];
                bvh[0]=smu[AVH +        n0*36 + pb+kl];
                bvh[1]=smu[AVH +        n0*36 + pb+kl+4];
                bvl[0]=smu[AVL +        n0*36 + pb+kl];
                bvl[1]=smu[AVL +        n0*36 + pb+kl+4];
                bwh[0]=smu[AVH + 2304 + n0*36 + pb+kl];
                bwh[1]=smu[AVH + 2304 + n0*36 + pb+kl+4];
                bwl[0]=smu[AVL + 2304 + n0*36 + pb+kl];
                bwl[1]=smu[AVL + 2304 + n0*36 + pb+kl+4];
                mma16(Or[nt], aph, bvh);
                mma16(Or[nt], aph, bvl);
                mma16(Or[nt], apl, bvh);
                mma16(Oi[nt], aph, bwh);
                mma16(Oi[nt], aph, bwl);
                mma16(Oi[nt], apl, bwh);
            }
        }
    }

    __syncthreads();
    const float inv0 = 1.f / sL[lr0];
    const float inv1 = 1.f / sL[lr1];
    #pragma unroll
    for (int nt = 0; nt < 2; ++nt) {
        const int h0 = wn*16 + nt*8 + 2*kl;
        const size_t rA = (size_t)(qbase + lr0);
        const size_t rB = (size_t)(qbase + lr1);
        *(float2*)(out + rA*H_ + h0) = make_float2(Or[nt][0]*inv0, Or[nt][1]*inv0);
        *(float2*)(out + rB*H_ + h0) = make_float2(Or[nt][2]*inv1, Or[nt][3]*inv1);
        *(float2*)(out + (size_t)M_*H_ + rA*H_ + h0) = make_float2(Oi[nt][0]*inv0, Oi[nt][1]*inv0);
        *(float2*)(out + (size_t)M_*H_ + rB*H_ + h0) = make_float2(Oi[nt][2]*inv1, Oi[nt][3]*inv1);
    }
}

// ---------------------------------------------------------------------------
extern "C" void kernel_launch(void* const* d_in, const int* in_sizes, int n_in,
                              void* d_out, int out_size)
{
    const float* xr  = (const float*)d_in[0];
    const float* xi  = (const float*)d_in[1];
    const float* Wkr = (const float*)d_in[2];
    const float* Wki = (const float*)d_in[3];
    const float* Wqr = (const float*)d_in[4];
    const float* Wqi = (const float*)d_in[5];
    const float* Wvr = (const float*)d_in[6];
    const float* Wvi = (const float*)d_in[7];

    cudaFuncSetAttribute(proj_kernel,
        cudaFuncAttributeMaxDynamicSharedMemorySize, PJ_U32*4);
    cudaFuncSetAttribute(attn_kernel,
        cudaFuncAttributeMaxDynamicSharedMemorySize, AT_BYTES);

    proj_kernel<<<(M_/128)*3, 256, PJ_U32*4>>>(xr, xi, Wkr, Wki, Wqr, Wqi, Wvr, Wvi);

    dim3 ag(T_/64, B_);
    attn_kernel<<<ag, 512, AT_BYTES>>>((float*)d_out);
}